// round 10
// baseline (speedup 1.0000x reference)
#include <cuda_runtime.h>
#include <cuda_bf16.h>
#include <cstdint>
#include <math.h>

#define NN 50000
#define CC 128
#define EE 800000
#define NPAD 50048            // 391 * 128
#define RTILES 391

// ---------------- scratch (static device globals; no allocation) ----------
__device__ float g_sA[NN * CC];
__device__ float g_sB[NN * CC];
__device__ float g_gi[NPAD * 3 * CC];
__device__ float g_gh[NPAD * 3 * CC];
__device__ float g_wcomb[384 * CC];
__device__ int   g_cnt[NN];
__device__ int   g_rowptr[NN + 1];
__device__ int   g_perm[EE];
__device__ int   g_bsum[64];

__device__ __nv_bfloat16 g_sxh[NPAD * CC];
__device__ __nv_bfloat16 g_sxl[NPAD * CC];
__device__ __nv_bfloat16 g_sph[NPAD * CC];
__device__ __nv_bfloat16 g_spl[NPAD * CC];
__device__ __nv_bfloat16 g_wch[384 * CC];
__device__ __nv_bfloat16 g_wcl[384 * CC];
__device__ __nv_bfloat16 g_whhh[384 * CC];
__device__ __nv_bfloat16 g_whhl[384 * CC];

// ---------------- PTX helpers ----------------------------------------------
__device__ __forceinline__ uint32_t smem_u32(const void* p) {
    uint32_t a;
    asm("{ .reg .u64 t; cvta.to.shared.u64 t, %1; cvt.u32.u64 %0, t; }" : "=r"(a) : "l"(p));
    return a;
}
__device__ __forceinline__ void ldsm4(uint32_t* r, uint32_t addr) {
    asm volatile("ldmatrix.sync.aligned.m8n8.x4.shared.b16 {%0,%1,%2,%3}, [%4];"
                 : "=r"(r[0]), "=r"(r[1]), "=r"(r[2]), "=r"(r[3]) : "r"(addr));
}
__device__ __forceinline__ void mma_bf16(float* d, const uint32_t* a,
                                         uint32_t b0, uint32_t b1) {
    asm volatile(
        "mma.sync.aligned.m16n8k16.row.col.f32.bf16.bf16.f32 "
        "{%0,%1,%2,%3}, {%4,%5,%6,%7}, {%8,%9}, {%0,%1,%2,%3};"
        : "+f"(d[0]), "+f"(d[1]), "+f"(d[2]), "+f"(d[3])
        : "r"(a[0]), "r"(a[1]), "r"(a[2]), "r"(a[3]), "r"(b0), "r"(b1));
}

// ---------------- small utility kernels -----------------------------------
__global__ void zero_int(int* p, int n) {
    int i = blockIdx.x * blockDim.x + threadIdx.x;
    if (i < n) p[i] = 0;
}

__global__ void zero_pad_bf16(__nv_bfloat16* a, __nv_bfloat16* b,
                              __nv_bfloat16* c, __nv_bfloat16* d) {
    int i = blockIdx.x * blockDim.x + threadIdx.x;
    int n = (NPAD - NN) * CC;
    if (i < n) {
        int off = NN * CC + i;
        __nv_bfloat16 z = __float2bfloat16(0.f);
        a[off] = z; b[off] = z; c[off] = z; d[off] = z;
    }
}

__global__ void count_k(const int* __restrict__ dst, int* __restrict__ cnt) {
    int e = blockIdx.x * blockDim.x + threadIdx.x;
    if (e < EE) {
        int d = dst[e];
        d = min(max(d, 0), NN - 1);
        atomicAdd(&cnt[d], 1);
    }
}

__global__ void scan_block(const int* __restrict__ cnt, int* __restrict__ excl,
                           int* __restrict__ bsum, int n) {
    __shared__ int sm[1024];
    int t = threadIdx.x;
    int g = blockIdx.x * 1024 + t;
    int v = (g < n) ? cnt[g] : 0;
    sm[t] = v;
    __syncthreads();
    for (int off = 1; off < 1024; off <<= 1) {
        int tv = 0;
        if (t >= off) tv = sm[t - off];
        __syncthreads();
        if (t >= off) sm[t] += tv;
        __syncthreads();
    }
    if (g < n) excl[g] = sm[t] - v;
    if (t == 1023) bsum[blockIdx.x] = sm[1023];
}

__global__ void scan_sums(int* bsum, int nb) {
    int run = 0;
    for (int i = 0; i < nb; i++) { int t = bsum[i]; bsum[i] = run; run += t; }
}

__global__ void add_off(int* __restrict__ rowptr, const int* __restrict__ bsum, int n) {
    int g = blockIdx.x * blockDim.x + threadIdx.x;
    if (g < n) rowptr[g] += bsum[g >> 10];
    if (g == 0) rowptr[n] = EE;
}

__global__ void fill_k(const int* __restrict__ src, const int* __restrict__ dst,
                       const int* __restrict__ rowptr, int* __restrict__ cur,
                       int* __restrict__ perm) {
    int e = blockIdx.x * blockDim.x + threadIdx.x;
    if (e < EE) {
        int d = dst[e];
        d = min(max(d, 0), NN - 1);
        int s = src[e];
        s = min(max(s, 0), NN - 1);
        int pos = rowptr[d] + atomicAdd(&cur[d], 1);
        if (pos >= 0 && pos < EE) perm[pos] = s;
    }
}

// ---------------- W_comb = W_ih @ W_lin (fp32, once) -----------------------
__global__ void wcomb_k(const float* __restrict__ W_ih, const float* __restrict__ W_lin,
                        float* __restrict__ W_comb) {
    int i = blockIdx.x;
    int j = threadIdx.x;
    float s = 0.f;
    #pragma unroll 8
    for (int k = 0; k < 128; k++)
        s += W_ih[i * 128 + k] * W_lin[k * 128 + j];
    W_comb[i * 128 + j] = s;
}

// ---------------- fp32 -> bf16 hi/lo split ---------------------------------
__global__ void conv_split(const float* __restrict__ x, __nv_bfloat16* __restrict__ hi,
                           __nv_bfloat16* __restrict__ lo, int n4) {
    int i = blockIdx.x * blockDim.x + threadIdx.x;
    if (i >= n4) return;
    float4 v = ((const float4*)x)[i];
    __nv_bfloat16 h0 = __float2bfloat16(v.x);
    __nv_bfloat16 h1 = __float2bfloat16(v.y);
    __nv_bfloat16 h2 = __float2bfloat16(v.z);
    __nv_bfloat16 h3 = __float2bfloat16(v.w);
    __nv_bfloat16 l0 = __float2bfloat16(v.x - __bfloat162float(h0));
    __nv_bfloat16 l1 = __float2bfloat16(v.y - __bfloat162float(h1));
    __nv_bfloat16 l2 = __float2bfloat16(v.z - __bfloat162float(h2));
    __nv_bfloat16 l3 = __float2bfloat16(v.w - __bfloat162float(h3));
    __nv_bfloat162* hp = (__nv_bfloat162*)hi;
    __nv_bfloat162* lp = (__nv_bfloat162*)lo;
    hp[i * 2 + 0] = __nv_bfloat162(h0, h1);
    hp[i * 2 + 1] = __nv_bfloat162(h2, h3);
    lp[i * 2 + 0] = __nv_bfloat162(l0, l1);
    lp[i * 2 + 1] = __nv_bfloat162(l2, l3);
}

// ---------------- hand mma split-bf16 GEMM ---------------------------------
// Y[NPAD, M] = (Ah+Al)[NPAD,128] @ ((Bh+Bl)[M,128])^T, drop Al*Bl.
// block tile 128x64, 128 threads (4 warps, 2x2), warp tile 64x32:
// 12 ldsm4 per warp per k-step for 48 MMAs -> 32 FLOP/B smem (vs 24 in R9).
// 104448 B smem -> 2 CTAs/SM.
#define LDSB 136
#define ROWB (LDSB * 2)                       // 272 bytes per smem row
#define A_T (128 * LDSB)                      // bf16 elems per A tile
#define B_T (64 * LDSB)
#define GT_SMEM ((2 * A_T + 2 * B_T) * 2)     // 104448 bytes

__global__ __launch_bounds__(128, 2)
void gemm_tc(const __nv_bfloat16* __restrict__ Ah, const __nv_bfloat16* __restrict__ Al,
             const __nv_bfloat16* __restrict__ Bh, const __nv_bfloat16* __restrict__ Bl,
             float* __restrict__ Y, int M) {
    extern __shared__ __nv_bfloat16 smb[];
    __nv_bfloat16* As_h = smb;
    __nv_bfloat16* As_l = smb + A_T;
    __nv_bfloat16* Bs_h = smb + 2 * A_T;
    __nv_bfloat16* Bs_l = smb + 2 * A_T + B_T;

    int row0 = blockIdx.x * 128;
    int col0 = blockIdx.y * 64;
    int t = threadIdx.x;

    // ---- global -> smem (A: 2048 uint4/tile; B: 1024 uint4/tile) ----
    {
        const uint4* gAh = (const uint4*)(Ah + (size_t)row0 * 128);
        const uint4* gAl = (const uint4*)(Al + (size_t)row0 * 128);
        #pragma unroll
        for (int i = 0; i < 16; i++) {
            int idx = t + i * 128;
            int r = idx >> 4, c = idx & 15;
            ((uint4*)((char*)As_h + r * ROWB))[c] = gAh[idx];
            ((uint4*)((char*)As_l + r * ROWB))[c] = gAl[idx];
        }
        const uint4* gBh = (const uint4*)(Bh + (size_t)col0 * 128);
        const uint4* gBl = (const uint4*)(Bl + (size_t)col0 * 128);
        #pragma unroll
        for (int i = 0; i < 8; i++) {
            int idx = t + i * 128;
            int r = idx >> 4, c = idx & 15;
            ((uint4*)((char*)Bs_h + r * ROWB))[c] = gBh[idx];
            ((uint4*)((char*)Bs_l + r * ROWB))[c] = gBl[idx];
        }
    }
    __syncthreads();

    int lane = t & 31;
    int wid = t >> 5;
    int wm = wid & 1;       // 64-row slab
    int wn = wid >> 1;      // 32-col slab

    // ldmatrix lane offset: (lane&15) = matrix row, (lane>>4) = 16B half
    uint32_t laneOff = (uint32_t)((lane & 15) * ROWB + (lane >> 4) * 16);
    uint32_t aH = smem_u32(As_h) + (uint32_t)(wm * 64) * ROWB + laneOff;
    uint32_t aL = aH + A_T * 2;
    uint32_t bH = smem_u32(Bs_h) + (uint32_t)(wn * 32) * ROWB + laneOff;
    uint32_t bL = bH + B_T * 2;

    float acc[4][4][4];     // [row frag f][col frag j][quad]
    #pragma unroll
    for (int f = 0; f < 4; f++)
        #pragma unroll
        for (int j = 0; j < 4; j++)
            #pragma unroll
            for (int q = 0; q < 4; q++) acc[f][j][q] = 0.f;

    #pragma unroll
    for (int ks = 0; ks < 8; ks++) {
        uint32_t kb = ks * 32;                 // 16 bf16 = 32 bytes
        uint32_t ah[4][4], bh2[2][4];
        #pragma unroll
        for (int f = 0; f < 4; f++) ldsm4(ah[f], aH + (uint32_t)(f * 16) * ROWB + kb);
        ldsm4(bh2[0], bH + kb);                // B(hi) n 0..15
        ldsm4(bh2[1], bH + 16 * ROWB + kb);    // B(hi) n 16..31
        // phase 1: ah x bh (16 independent MMAs)
        #pragma unroll
        for (int f = 0; f < 4; f++) {
            mma_bf16(acc[f][0], ah[f], bh2[0][0], bh2[0][2]);
            mma_bf16(acc[f][1], ah[f], bh2[0][1], bh2[0][3]);
            mma_bf16(acc[f][2], ah[f], bh2[1][0], bh2[1][2]);
            mma_bf16(acc[f][3], ah[f], bh2[1][1], bh2[1][3]);
        }
        // phase 2: ah x bl (bl transient)
        {
            uint32_t bl2[2][4];
            ldsm4(bl2[0], bL + kb);
            ldsm4(bl2[1], bL + 16 * ROWB + kb);
            #pragma unroll
            for (int f = 0; f < 4; f++) {
                mma_bf16(acc[f][0], ah[f], bl2[0][0], bl2[0][2]);
                mma_bf16(acc[f][1], ah[f], bl2[0][1], bl2[0][3]);
                mma_bf16(acc[f][2], ah[f], bl2[1][0], bl2[1][2]);
                mma_bf16(acc[f][3], ah[f], bl2[1][1], bl2[1][3]);
            }
        }
        // phase 3: al x bh (al reuses ah's registers; ah dead)
        #pragma unroll
        for (int f = 0; f < 4; f++) {
            uint32_t al[4];
            ldsm4(al, aL + (uint32_t)(f * 16) * ROWB + kb);
            mma_bf16(acc[f][0], al, bh2[0][0], bh2[0][2]);
            mma_bf16(acc[f][1], al, bh2[0][1], bh2[0][3]);
            mma_bf16(acc[f][2], al, bh2[1][0], bh2[1][2]);
            mma_bf16(acc[f][3], al, bh2[1][1], bh2[1][3]);
        }
    }

    // ---- epilogue: d regs -> Y (float2 stores) ----
    int r = row0 + wm * 64 + (lane >> 2);
    int c = col0 + wn * 32 + (lane & 3) * 2;
    #pragma unroll
    for (int f = 0; f < 4; f++) {
        #pragma unroll
        for (int j = 0; j < 4; j++) {
            float2 v0 = make_float2(acc[f][j][0], acc[f][j][1]);
            float2 v1 = make_float2(acc[f][j][2], acc[f][j][3]);
            *(float2*)&Y[(size_t)(r + f * 16) * M + c + j * 8] = v0;
            *(float2*)&Y[(size_t)(r + f * 16 + 8) * M + c + j * 8] = v1;
        }
    }
}

// ---------------- aggregation ------------------------------------------------
__global__ void aggregate(const float* __restrict__ st, const int* __restrict__ rowptr,
                          const int* __restrict__ perm,
                          __nv_bfloat16* __restrict__ ph, __nv_bfloat16* __restrict__ pl) {
    int i = blockIdx.x;
    int c = threadIdx.x;
    int s0 = rowptr[i], s1 = rowptr[i + 1];
    float a0 = 0.f, a1 = 0.f, a2 = 0.f, a3 = 0.f;
    int e = s0;
    for (; e + 3 < s1; e += 4) {
        int p0 = perm[e], p1 = perm[e + 1], p2 = perm[e + 2], p3 = perm[e + 3];
        a0 += st[p0 * 128 + c];
        a1 += st[p1 * 128 + c];
        a2 += st[p2 * 128 + c];
        a3 += st[p3 * 128 + c];
    }
    for (; e < s1; e++) a0 += st[perm[e] * 128 + c];
    float s = (a0 + a1) + (a2 + a3);
    __nv_bfloat16 h = __float2bfloat16(s);
    ph[i * 128 + c] = h;
    pl[i * 128 + c] = __float2bfloat16(s - __bfloat162float(h));
}

// ---------------- GRU elementwise, float4 vectorized ------------------------
__global__ void gru_k(const float* __restrict__ gi, const float* __restrict__ gh,
                      const float* __restrict__ b_ih, const float* __restrict__ b_hh,
                      const float* __restrict__ h, float* __restrict__ out,
                      __nv_bfloat16* __restrict__ oh, __nv_bfloat16* __restrict__ ol,
                      int n4) {
    int idx = blockIdx.x * blockDim.x + threadIdx.x;
    if (idx >= n4) return;
    int i = idx >> 5;
    int c4 = (idx & 31) * 4;
    const float4* gir = (const float4*)(gi + (size_t)i * 384 + c4);
    const float4* ghr = (const float4*)(gh + (size_t)i * 384 + c4);
    float4 ir = gir[0],  iz = gir[32],  in_ = gir[64];
    float4 hr = ghr[0],  hz = ghr[32],  hn = ghr[64];
    float4 bir = *(const float4*)(b_ih + c4);
    float4 biz = *(const float4*)(b_ih + 128 + c4);
    float4 bin = *(const float4*)(b_ih + 256 + c4);
    float4 bhr = *(const float4*)(b_hh + c4);
    float4 bhz = *(const float4*)(b_hh + 128 + c4);
    float4 bhn = *(const float4*)(b_hh + 256 + c4);
    float4 hv = *(const float4*)(h + (size_t)i * 128 + c4);

    float o[4], ohh[4], oll[4];
    #pragma unroll
    for (int q = 0; q < 4; q++) {
        float irq = ((&ir.x)[q] + (&bir.x)[q]) + ((&hr.x)[q] + (&bhr.x)[q]);
        float izq = ((&iz.x)[q] + (&biz.x)[q]) + ((&hz.x)[q] + (&bhz.x)[q]);
        float inq = (&in_.x)[q] + (&bin.x)[q];
        float hnq = (&hn.x)[q] + (&bhn.x)[q];
        float r = 1.f / (1.f + expf(-irq));
        float z = 1.f / (1.f + expf(-izq));
        float nval = tanhf(inq + r * hnq);
        float val = (1.f - z) * nval + z * (&hv.x)[q];
        o[q] = val;
        __nv_bfloat16 vh = __float2bfloat16(val);
        ohh[q] = __bfloat162float(vh);
        oll[q] = val - ohh[q];
    }
    *(float4*)(out + (size_t)i * 128 + c4) = make_float4(o[0], o[1], o[2], o[3]);
    __nv_bfloat162* ohp = (__nv_bfloat162*)(oh + (size_t)i * 128 + c4);
    __nv_bfloat162* olp = (__nv_bfloat162*)(ol + (size_t)i * 128 + c4);
    ohp[0] = __nv_bfloat162(__float2bfloat16(ohh[0]), __float2bfloat16(ohh[1]));
    ohp[1] = __nv_bfloat162(__float2bfloat16(ohh[2]), __float2bfloat16(ohh[3]));
    olp[0] = __nv_bfloat162(__float2bfloat16(oll[0]), __float2bfloat16(oll[1]));
    olp[1] = __nv_bfloat162(__float2bfloat16(oll[2]), __float2bfloat16(oll[3]));
}

// ---------------- launcher --------------------------------------------------
extern "C" void kernel_launch(void* const* d_in, const int* in_sizes, int n_in,
                              void* d_out, int out_size) {
    const float* x     = (const float*)d_in[0];
    const int*   ei    = (const int*)d_in[1];
    const float* W_lin = (const float*)d_in[2];
    const float* W_ih  = (const float*)d_in[3];
    const float* W_hh  = (const float*)d_in[4];
    const float* b_ih  = (const float*)d_in[5];
    const float* b_hh  = (const float*)d_in[6];
    float* out = (float*)d_out;

    const int* src = ei;
    const int* dst = ei + EE;

    float *sA_, *sB_, *gi_, *gh_, *wc_;
    int *cnt_, *rp_, *perm_, *bsum_;
    __nv_bfloat16 *sxh_, *sxl_, *sph_, *spl_, *wch_, *wcl_, *whhh_, *whhl_;
    cudaGetSymbolAddress((void**)&sA_,   g_sA);
    cudaGetSymbolAddress((void**)&sB_,   g_sB);
    cudaGetSymbolAddress((void**)&gi_,   g_gi);
    cudaGetSymbolAddress((void**)&gh_,   g_gh);
    cudaGetSymbolAddress((void**)&wc_,   g_wcomb);
    cudaGetSymbolAddress((void**)&cnt_,  g_cnt);
    cudaGetSymbolAddress((void**)&rp_,   g_rowptr);
    cudaGetSymbolAddress((void**)&perm_, g_perm);
    cudaGetSymbolAddress((void**)&bsum_, g_bsum);
    cudaGetSymbolAddress((void**)&sxh_,  g_sxh);
    cudaGetSymbolAddress((void**)&sxl_,  g_sxl);
    cudaGetSymbolAddress((void**)&sph_,  g_sph);
    cudaGetSymbolAddress((void**)&spl_,  g_spl);
    cudaGetSymbolAddress((void**)&wch_,  g_wch);
    cudaGetSymbolAddress((void**)&wcl_,  g_wcl);
    cudaGetSymbolAddress((void**)&whhh_, g_whhh);
    cudaGetSymbolAddress((void**)&whhl_, g_whhl);

    cudaFuncSetAttribute(gemm_tc, cudaFuncAttributeMaxDynamicSharedMemorySize, GT_SMEM);

    const int NB_SCAN = (NN + 1023) / 1024;
    const int N4 = NN * CC / 4;
    const dim3 gg(RTILES, 6);                 // 128x64 tiles over [NPAD, 384]

    // launch order: gemm_tc at my #4 (ncu -s 5 -c 1 lands there)
    conv_split<<<(N4 + 255) / 256, 256>>>(x, sxh_, sxl_, N4);                          // 1
    conv_split<<<(384 * CC / 4 + 255) / 256, 256>>>(W_hh, whhh_, whhl_, 384 * CC / 4); // 2
    zero_pad_bf16<<<((NPAD - NN) * CC + 255) / 256, 256>>>(sxh_, sxl_, sph_, spl_);    // 3
    gemm_tc<<<gg, 128, GT_SMEM>>>(sxh_, sxl_, whhh_, whhl_, gh_, 384);                 // 4 (profiled)

    wcomb_k<<<384, 128>>>(W_ih, W_lin, wc_);
    conv_split<<<(384 * CC / 4 + 255) / 256, 256>>>(wc_, wch_, wcl_, 384 * CC / 4);

    // ---- build CSR ----
    zero_int <<<(NN + 255) / 256, 256>>>(cnt_, NN);
    count_k  <<<(EE + 255) / 256, 256>>>(dst, cnt_);
    scan_block<<<NB_SCAN, 1024>>>(cnt_, rp_, bsum_, NN);
    scan_sums <<<1, 1>>>(bsum_, NB_SCAN);
    add_off   <<<(NN + 255) / 256, 256>>>(rp_, bsum_, NN);
    zero_int  <<<(NN + 255) / 256, 256>>>(cnt_, NN);
    fill_k    <<<(EE + 255) / 256, 256>>>(src, dst, rp_, cnt_, perm_);

    // ---- 3 propagation steps ----
    const float* sin = x;
    for (int step = 0; step < 3; step++) {
        float* sout = (step == 2) ? out : ((step == 0) ? sA_ : sB_);

        if (step > 0)   // step 0's gh computed at launch 4
            gemm_tc<<<gg, 128, GT_SMEM>>>(sxh_, sxl_, whhh_, whhl_, gh_, 384);
        aggregate<<<NN, 128>>>(sin, rp_, perm_, sph_, spl_);
        gemm_tc<<<gg, 128, GT_SMEM>>>(sph_, spl_, wch_, wcl_, gi_, 384);
        gru_k<<<(N4 + 255) / 256, 256>>>(gi_, gh_, b_ih, b_hh, sin, sout,
                                         sxh_, sxl_, N4);
        sin = sout;
    }
}

// round 11
// speedup vs baseline: 1.0708x; 1.0708x over previous
#include <cuda_runtime.h>
#include <cuda_bf16.h>
#include <cstdint>
#include <math.h>

#define NN 50000
#define CC 128
#define EE 800000
#define NPAD 50048            // 391 * 128
#define RTILES 391

// ---------------- scratch (static device globals; no allocation) ----------
__device__ float g_sA[NN * CC];
__device__ float g_sB[NN * CC];
__device__ float g_gi[NPAD * 3 * CC];
__device__ float g_gh[NPAD * 3 * CC];
__device__ float g_wcomb[384 * CC];
__device__ int   g_cnt[NN];
__device__ int   g_rowptr[NN + 1];
__device__ int   g_perm[EE];
__device__ int   g_bsum[64];

__device__ __nv_bfloat16 g_sxh[NPAD * CC];
__device__ __nv_bfloat16 g_sxl[NPAD * CC];
__device__ __nv_bfloat16 g_sph[NPAD * CC];
__device__ __nv_bfloat16 g_spl[NPAD * CC];
__device__ __nv_bfloat16 g_wch[384 * CC];
__device__ __nv_bfloat16 g_wcl[384 * CC];
__device__ __nv_bfloat16 g_whhh[384 * CC];
__device__ __nv_bfloat16 g_whhl[384 * CC];

// ---------------- PTX helpers ----------------------------------------------
__device__ __forceinline__ uint32_t smem_u32(const void* p) {
    uint32_t a;
    asm("{ .reg .u64 t; cvta.to.shared.u64 t, %1; cvt.u32.u64 %0, t; }" : "=r"(a) : "l"(p));
    return a;
}
__device__ __forceinline__ void ldsm4(uint32_t* r, uint32_t addr) {
    asm volatile("ldmatrix.sync.aligned.m8n8.x4.shared.b16 {%0,%1,%2,%3}, [%4];"
                 : "=r"(r[0]), "=r"(r[1]), "=r"(r[2]), "=r"(r[3]) : "r"(addr));
}
__device__ __forceinline__ void mma_bf16(float* d, const uint32_t* a,
                                         uint32_t b0, uint32_t b1) {
    asm volatile(
        "mma.sync.aligned.m16n8k16.row.col.f32.bf16.bf16.f32 "
        "{%0,%1,%2,%3}, {%4,%5,%6,%7}, {%8,%9}, {%0,%1,%2,%3};"
        : "+f"(d[0]), "+f"(d[1]), "+f"(d[2]), "+f"(d[3])
        : "r"(a[0]), "r"(a[1]), "r"(a[2]), "r"(a[3]), "r"(b0), "r"(b1));
}

// ---------------- small utility kernels -----------------------------------
__global__ void zero_int(int* p, int n) {
    int i = blockIdx.x * blockDim.x + threadIdx.x;
    if (i < n) p[i] = 0;
}

__global__ void zero_pad_bf16(__nv_bfloat16* a, __nv_bfloat16* b,
                              __nv_bfloat16* c, __nv_bfloat16* d) {
    int i = blockIdx.x * blockDim.x + threadIdx.x;
    int n = (NPAD - NN) * CC;
    if (i < n) {
        int off = NN * CC + i;
        __nv_bfloat16 z = __float2bfloat16(0.f);
        a[off] = z; b[off] = z; c[off] = z; d[off] = z;
    }
}

__global__ void count_k(const int* __restrict__ dst, int* __restrict__ cnt) {
    int e = blockIdx.x * blockDim.x + threadIdx.x;
    if (e < EE) {
        int d = dst[e];
        d = min(max(d, 0), NN - 1);
        atomicAdd(&cnt[d], 1);
    }
}

__global__ void scan_block(const int* __restrict__ cnt, int* __restrict__ excl,
                           int* __restrict__ bsum, int n) {
    __shared__ int sm[1024];
    int t = threadIdx.x;
    int g = blockIdx.x * 1024 + t;
    int v = (g < n) ? cnt[g] : 0;
    sm[t] = v;
    __syncthreads();
    for (int off = 1; off < 1024; off <<= 1) {
        int tv = 0;
        if (t >= off) tv = sm[t - off];
        __syncthreads();
        if (t >= off) sm[t] += tv;
        __syncthreads();
    }
    if (g < n) excl[g] = sm[t] - v;
    if (t == 1023) bsum[blockIdx.x] = sm[1023];
}

__global__ void scan_sums(int* bsum, int nb) {
    int run = 0;
    for (int i = 0; i < nb; i++) { int t = bsum[i]; bsum[i] = run; run += t; }
}

__global__ void add_off(int* __restrict__ rowptr, const int* __restrict__ bsum, int n) {
    int g = blockIdx.x * blockDim.x + threadIdx.x;
    if (g < n) rowptr[g] += bsum[g >> 10];
    if (g == 0) rowptr[n] = EE;
}

__global__ void fill_k(const int* __restrict__ src, const int* __restrict__ dst,
                       const int* __restrict__ rowptr, int* __restrict__ cur,
                       int* __restrict__ perm) {
    int e = blockIdx.x * blockDim.x + threadIdx.x;
    if (e < EE) {
        int d = dst[e];
        d = min(max(d, 0), NN - 1);
        int s = src[e];
        s = min(max(s, 0), NN - 1);
        int pos = rowptr[d] + atomicAdd(&cur[d], 1);
        if (pos >= 0 && pos < EE) perm[pos] = s;
    }
}

// ---------------- W_comb = W_ih @ W_lin (fp32, once) -----------------------
__global__ void wcomb_k(const float* __restrict__ W_ih, const float* __restrict__ W_lin,
                        float* __restrict__ W_comb) {
    int i = blockIdx.x;
    int j = threadIdx.x;
    float s = 0.f;
    #pragma unroll 8
    for (int k = 0; k < 128; k++)
        s += W_ih[i * 128 + k] * W_lin[k * 128 + j];
    W_comb[i * 128 + j] = s;
}

// ---------------- fp32 -> bf16 hi/lo split ---------------------------------
__global__ void conv_split(const float* __restrict__ x, __nv_bfloat16* __restrict__ hi,
                           __nv_bfloat16* __restrict__ lo, int n4) {
    int i = blockIdx.x * blockDim.x + threadIdx.x;
    if (i >= n4) return;
    float4 v = ((const float4*)x)[i];
    __nv_bfloat16 h0 = __float2bfloat16(v.x);
    __nv_bfloat16 h1 = __float2bfloat16(v.y);
    __nv_bfloat16 h2 = __float2bfloat16(v.z);
    __nv_bfloat16 h3 = __float2bfloat16(v.w);
    __nv_bfloat16 l0 = __float2bfloat16(v.x - __bfloat162float(h0));
    __nv_bfloat16 l1 = __float2bfloat16(v.y - __bfloat162float(h1));
    __nv_bfloat16 l2 = __float2bfloat16(v.z - __bfloat162float(h2));
    __nv_bfloat16 l3 = __float2bfloat16(v.w - __bfloat162float(h3));
    __nv_bfloat162* hp = (__nv_bfloat162*)hi;
    __nv_bfloat162* lp = (__nv_bfloat162*)lo;
    hp[i * 2 + 0] = __nv_bfloat162(h0, h1);
    hp[i * 2 + 1] = __nv_bfloat162(h2, h3);
    lp[i * 2 + 0] = __nv_bfloat162(l0, l1);
    lp[i * 2 + 1] = __nv_bfloat162(l2, l3);
}

// ---------------- hand mma split-bf16 GEMM (R9 config: best known) ---------
// block tile 128x64, 256 threads (8 warps, 4x2), warp tile 32x32.
#define LDSB 136
#define ROWB (LDSB * 2)                       // 272 bytes per smem row
#define A_T (128 * LDSB)
#define B_T (64 * LDSB)
#define GT_SMEM ((2 * A_T + 2 * B_T) * 2)     // 104448 bytes

__global__ __launch_bounds__(256, 2)
void gemm_tc(const __nv_bfloat16* __restrict__ Ah, const __nv_bfloat16* __restrict__ Al,
             const __nv_bfloat16* __restrict__ Bh, const __nv_bfloat16* __restrict__ Bl,
             float* __restrict__ Y, int M) {
    extern __shared__ __nv_bfloat16 smb[];
    __nv_bfloat16* As_h = smb;
    __nv_bfloat16* As_l = smb + A_T;
    __nv_bfloat16* Bs_h = smb + 2 * A_T;
    __nv_bfloat16* Bs_l = smb + 2 * A_T + B_T;

    int row0 = blockIdx.x * 128;
    int col0 = blockIdx.y * 64;
    int t = threadIdx.x;

    {
        const uint4* gAh = (const uint4*)(Ah + (size_t)row0 * 128);
        const uint4* gAl = (const uint4*)(Al + (size_t)row0 * 128);
        #pragma unroll
        for (int i = 0; i < 8; i++) {
            int idx = t + i * 256;
            int r = idx >> 4, c = idx & 15;
            ((uint4*)((char*)As_h + r * ROWB))[c] = gAh[idx];
            ((uint4*)((char*)As_l + r * ROWB))[c] = gAl[idx];
        }
        const uint4* gBh = (const uint4*)(Bh + (size_t)col0 * 128);
        const uint4* gBl = (const uint4*)(Bl + (size_t)col0 * 128);
        #pragma unroll
        for (int i = 0; i < 4; i++) {
            int idx = t + i * 256;
            int r = idx >> 4, c = idx & 15;
            ((uint4*)((char*)Bs_h + r * ROWB))[c] = gBh[idx];
            ((uint4*)((char*)Bs_l + r * ROWB))[c] = gBl[idx];
        }
    }
    __syncthreads();

    int lane = t & 31;
    int wid = t >> 5;
    int wm = wid & 3;
    int wn = wid >> 2;

    uint32_t laneOff = (uint32_t)((lane & 15) * ROWB + (lane >> 4) * 16);
    uint32_t aH = smem_u32(As_h) + (uint32_t)(wm * 32) * ROWB + laneOff;
    uint32_t aL = aH + A_T * 2;
    uint32_t bH = smem_u32(Bs_h) + (uint32_t)(wn * 32) * ROWB + laneOff;
    uint32_t bL = bH + B_T * 2;

    float acc[2][4][4];
    #pragma unroll
    for (int i = 0; i < 2; i++)
        #pragma unroll
        for (int j = 0; j < 4; j++)
            #pragma unroll
            for (int q = 0; q < 4; q++) acc[i][j][q] = 0.f;

    #pragma unroll
    for (int ks = 0; ks < 8; ks++) {
        uint32_t kb = ks * 32;
        uint32_t a0[4], a1[4], p0[4], p1[4];
        ldsm4(a0, aH + kb);
        ldsm4(a1, aH + 16 * ROWB + kb);
        ldsm4(p0, bH + kb);
        ldsm4(p1, bH + 16 * ROWB + kb);
        mma_bf16(acc[0][0], a0, p0[0], p0[2]);
        mma_bf16(acc[0][1], a0, p0[1], p0[3]);
        mma_bf16(acc[0][2], a0, p1[0], p1[2]);
        mma_bf16(acc[0][3], a0, p1[1], p1[3]);
        mma_bf16(acc[1][0], a1, p0[0], p0[2]);
        mma_bf16(acc[1][1], a1, p0[1], p0[3]);
        mma_bf16(acc[1][2], a1, p1[0], p1[2]);
        mma_bf16(acc[1][3], a1, p1[1], p1[3]);
        uint32_t c0[4], c1[4];
        ldsm4(c0, aL + kb);
        ldsm4(c1, aL + 16 * ROWB + kb);
        mma_bf16(acc[0][0], c0, p0[0], p0[2]);
        mma_bf16(acc[0][1], c0, p0[1], p0[3]);
        mma_bf16(acc[0][2], c0, p1[0], p1[2]);
        mma_bf16(acc[0][3], c0, p1[1], p1[3]);
        mma_bf16(acc[1][0], c1, p0[0], p0[2]);
        mma_bf16(acc[1][1], c1, p0[1], p0[3]);
        mma_bf16(acc[1][2], c1, p1[0], p1[2]);
        mma_bf16(acc[1][3], c1, p1[1], p1[3]);
        uint32_t q0[4], q1[4];
        ldsm4(q0, bL + kb);
        ldsm4(q1, bL + 16 * ROWB + kb);
        mma_bf16(acc[0][0], a0, q0[0], q0[2]);
        mma_bf16(acc[0][1], a0, q0[1], q0[3]);
        mma_bf16(acc[0][2], a0, q1[0], q1[2]);
        mma_bf16(acc[0][3], a0, q1[1], q1[3]);
        mma_bf16(acc[1][0], a1, q0[0], q0[2]);
        mma_bf16(acc[1][1], a1, q0[1], q0[3]);
        mma_bf16(acc[1][2], a1, q1[0], q1[2]);
        mma_bf16(acc[1][3], a1, q1[1], q1[3]);
    }

    int r = row0 + wm * 32 + (lane >> 2);
    int c = col0 + wn * 32 + (lane & 3) * 2;
    #pragma unroll
    for (int i = 0; i < 2; i++) {
        #pragma unroll
        for (int j = 0; j < 4; j++) {
            float2 v0 = make_float2(acc[i][j][0], acc[i][j][1]);
            float2 v1 = make_float2(acc[i][j][2], acc[i][j][3]);
            *(float2*)&Y[(size_t)(r + i * 16) * M + c + j * 8] = v0;
            *(float2*)&Y[(size_t)(r + i * 16 + 8) * M + c + j * 8] = v1;
        }
    }
}

// ---------------- aggregation ------------------------------------------------
__global__ void aggregate(const float* __restrict__ st, const int* __restrict__ rowptr,
                          const int* __restrict__ perm,
                          __nv_bfloat16* __restrict__ ph, __nv_bfloat16* __restrict__ pl) {
    int i = blockIdx.x;
    int c = threadIdx.x;
    int s0 = rowptr[i], s1 = rowptr[i + 1];
    float a0 = 0.f, a1 = 0.f, a2 = 0.f, a3 = 0.f;
    int e = s0;
    for (; e + 3 < s1; e += 4) {
        int p0 = perm[e], p1 = perm[e + 1], p2 = perm[e + 2], p3 = perm[e + 3];
        a0 += st[p0 * 128 + c];
        a1 += st[p1 * 128 + c];
        a2 += st[p2 * 128 + c];
        a3 += st[p3 * 128 + c];
    }
    for (; e < s1; e++) a0 += st[perm[e] * 128 + c];
    float s = (a0 + a1) + (a2 + a3);
    __nv_bfloat16 h = __float2bfloat16(s);
    ph[i * 128 + c] = h;
    pl[i * 128 + c] = __float2bfloat16(s - __bfloat162float(h));
}

// ---------------- GRU elementwise, float4 vectorized ------------------------
__global__ void gru_k(const float* __restrict__ gi, const float* __restrict__ gh,
                      const float* __restrict__ b_ih, const float* __restrict__ b_hh,
                      const float* __restrict__ h, float* __restrict__ out,
                      __nv_bfloat16* __restrict__ oh, __nv_bfloat16* __restrict__ ol,
                      int n4) {
    int idx = blockIdx.x * blockDim.x + threadIdx.x;
    if (idx >= n4) return;
    int i = idx >> 5;
    int c4 = (idx & 31) * 4;
    const float4* gir = (const float4*)(gi + (size_t)i * 384 + c4);
    const float4* ghr = (const float4*)(gh + (size_t)i * 384 + c4);
    float4 ir = gir[0],  iz = gir[32],  in_ = gir[64];
    float4 hr = ghr[0],  hz = ghr[32],  hn = ghr[64];
    float4 bir = *(const float4*)(b_ih + c4);
    float4 biz = *(const float4*)(b_ih + 128 + c4);
    float4 bin = *(const float4*)(b_ih + 256 + c4);
    float4 bhr = *(const float4*)(b_hh + c4);
    float4 bhz = *(const float4*)(b_hh + 128 + c4);
    float4 bhn = *(const float4*)(b_hh + 256 + c4);
    float4 hv = *(const float4*)(h + (size_t)i * 128 + c4);

    float o[4], ohh[4], oll[4];
    #pragma unroll
    for (int q = 0; q < 4; q++) {
        float irq = ((&ir.x)[q] + (&bir.x)[q]) + ((&hr.x)[q] + (&bhr.x)[q]);
        float izq = ((&iz.x)[q] + (&biz.x)[q]) + ((&hz.x)[q] + (&bhz.x)[q]);
        float inq = (&in_.x)[q] + (&bin.x)[q];
        float hnq = (&hn.x)[q] + (&bhn.x)[q];
        float r = 1.f / (1.f + expf(-irq));
        float z = 1.f / (1.f + expf(-izq));
        float nval = tanhf(inq + r * hnq);
        float val = (1.f - z) * nval + z * (&hv.x)[q];
        o[q] = val;
        __nv_bfloat16 vh = __float2bfloat16(val);
        ohh[q] = __bfloat162float(vh);
        oll[q] = val - ohh[q];
    }
    *(float4*)(out + (size_t)i * 128 + c4) = make_float4(o[0], o[1], o[2], o[3]);
    __nv_bfloat162* ohp = (__nv_bfloat162*)(oh + (size_t)i * 128 + c4);
    __nv_bfloat162* olp = (__nv_bfloat162*)(ol + (size_t)i * 128 + c4);
    ohp[0] = __nv_bfloat162(__float2bfloat16(ohh[0]), __float2bfloat16(ohh[1]));
    ohp[1] = __nv_bfloat162(__float2bfloat16(ohh[2]), __float2bfloat16(ohh[3]));
    olp[0] = __nv_bfloat162(__float2bfloat16(oll[0]), __float2bfloat16(oll[1]));
    olp[1] = __nv_bfloat162(__float2bfloat16(oll[2]), __float2bfloat16(oll[3]));
}

// ---------------- launcher --------------------------------------------------
extern "C" void kernel_launch(void* const* d_in, const int* in_sizes, int n_in,
                              void* d_out, int out_size) {
    const float* x     = (const float*)d_in[0];
    const int*   ei    = (const int*)d_in[1];
    const float* W_lin = (const float*)d_in[2];
    const float* W_ih  = (const float*)d_in[3];
    const float* W_hh  = (const float*)d_in[4];
    const float* b_ih  = (const float*)d_in[5];
    const float* b_hh  = (const float*)d_in[6];
    float* out = (float*)d_out;

    const int* src = ei;
    const int* dst = ei + EE;

    float *sA_, *sB_, *gi_, *gh_, *wc_;
    int *cnt_, *rp_, *perm_, *bsum_;
    __nv_bfloat16 *sxh_, *sxl_, *sph_, *spl_, *wch_, *wcl_, *whhh_, *whhl_;
    cudaGetSymbolAddress((void**)&sA_,   g_sA);
    cudaGetSymbolAddress((void**)&sB_,   g_sB);
    cudaGetSymbolAddress((void**)&gi_,   g_gi);
    cudaGetSymbolAddress((void**)&gh_,   g_gh);
    cudaGetSymbolAddress((void**)&wc_,   g_wcomb);
    cudaGetSymbolAddress((void**)&cnt_,  g_cnt);
    cudaGetSymbolAddress((void**)&rp_,   g_rowptr);
    cudaGetSymbolAddress((void**)&perm_, g_perm);
    cudaGetSymbolAddress((void**)&bsum_, g_bsum);
    cudaGetSymbolAddress((void**)&sxh_,  g_sxh);
    cudaGetSymbolAddress((void**)&sxl_,  g_sxl);
    cudaGetSymbolAddress((void**)&sph_,  g_sph);
    cudaGetSymbolAddress((void**)&spl_,  g_spl);
    cudaGetSymbolAddress((void**)&wch_,  g_wch);
    cudaGetSymbolAddress((void**)&wcl_,  g_wcl);
    cudaGetSymbolAddress((void**)&whhh_, g_whhh);
    cudaGetSymbolAddress((void**)&whhl_, g_whhl);

    cudaFuncSetAttribute(gemm_tc, cudaFuncAttributeMaxDynamicSharedMemorySize, GT_SMEM);

    // side stream + events for fork/join (host objects; few calls total,
    // leaked intentionally - destroying a capturing stream is illegal)
    cudaStream_t s2;
    cudaStreamCreateWithFlags(&s2, cudaStreamNonBlocking);
    cudaEvent_t evRoot, evCSR, evGru1, evGh1, evGru2, evGh2;
    cudaEventCreateWithFlags(&evRoot, cudaEventDisableTiming);
    cudaEventCreateWithFlags(&evCSR,  cudaEventDisableTiming);
    cudaEventCreateWithFlags(&evGru1, cudaEventDisableTiming);
    cudaEventCreateWithFlags(&evGh1,  cudaEventDisableTiming);
    cudaEventCreateWithFlags(&evGru2, cudaEventDisableTiming);
    cudaEventCreateWithFlags(&evGh2,  cudaEventDisableTiming);

    const int NB_SCAN = (NN + 1023) / 1024;
    const int N4 = NN * CC / 4;
    const dim3 gg(RTILES, 6);

    // ---- main stream: splits + step-0 gh GEMM (gemm_tc = my launch #4) ----
    conv_split<<<(N4 + 255) / 256, 256>>>(x, sxh_, sxl_, N4);                          // 1
    conv_split<<<(384 * CC / 4 + 255) / 256, 256>>>(W_hh, whhh_, whhl_, 384 * CC / 4); // 2
    zero_pad_bf16<<<((NPAD - NN) * CC + 255) / 256, 256>>>(sxh_, sxl_, sph_, spl_);    // 3
    gemm_tc<<<gg, 256, GT_SMEM>>>(sxh_, sxl_, whhh_, whhl_, gh_, 384);                 // 4 (profiled)
    wcomb_k<<<384, 128>>>(W_ih, W_lin, wc_);
    conv_split<<<(384 * CC / 4 + 255) / 256, 256>>>(wc_, wch_, wcl_, 384 * CC / 4);

    // ---- side stream: CSR build, overlapping the above ----
    cudaEventRecord(evRoot, 0);
    cudaStreamWaitEvent(s2, evRoot, 0);
    zero_int <<<(NN + 255) / 256, 256, 0, s2>>>(cnt_, NN);
    count_k  <<<(EE + 255) / 256, 256, 0, s2>>>(dst, cnt_);
    scan_block<<<NB_SCAN, 1024, 0, s2>>>(cnt_, rp_, bsum_, NN);
    scan_sums <<<1, 1, 0, s2>>>(bsum_, NB_SCAN);
    add_off   <<<(NN + 255) / 256, 256, 0, s2>>>(rp_, bsum_, NN);
    zero_int  <<<(NN + 255) / 256, 256, 0, s2>>>(cnt_, NN);
    fill_k    <<<(EE + 255) / 256, 256, 0, s2>>>(src, dst, rp_, cnt_, perm_);
    cudaEventRecord(evCSR, s2);
    cudaStreamWaitEvent(0, evCSR, 0);

    // ---- step 0 (gh done above) ----
    aggregate<<<NN, 128>>>(x, rp_, perm_, sph_, spl_);
    gemm_tc<<<gg, 256, GT_SMEM>>>(sph_, spl_, wch_, wcl_, gi_, 384);
    gru_k<<<(N4 + 255) / 256, 256>>>(gi_, gh_, b_ih, b_hh, x, sA_, sxh_, sxl_, N4);

    // ---- steps 1, 2: gh GEMM (s2) overlaps aggregate+gi GEMM (main) ----
    {
        // step 1
        cudaEventRecord(evGru1, 0);
        cudaStreamWaitEvent(s2, evGru1, 0);
        gemm_tc<<<gg, 256, GT_SMEM, s2>>>(sxh_, sxl_, whhh_, whhl_, gh_, 384);
        cudaEventRecord(evGh1, s2);
        aggregate<<<NN, 128>>>(sA_, rp_, perm_, sph_, spl_);
        gemm_tc<<<gg, 256, GT_SMEM>>>(sph_, spl_, wch_, wcl_, gi_, 384);
        cudaStreamWaitEvent(0, evGh1, 0);
        gru_k<<<(N4 + 255) / 256, 256>>>(gi_, gh_, b_ih, b_hh, sA_, sB_, sxh_, sxl_, N4);

        // step 2
        cudaEventRecord(evGru2, 0);
        cudaStreamWaitEvent(s2, evGru2, 0);
        gemm_tc<<<gg, 256, GT_SMEM, s2>>>(sxh_, sxl_, whhh_, whhl_, gh_, 384);
        cudaEventRecord(evGh2, s2);
        aggregate<<<NN, 128>>>(sB_, rp_, perm_, sph_, spl_);
        gemm_tc<<<gg, 256, GT_SMEM>>>(sph_, spl_, wch_, wcl_, gi_, 384);
        cudaStreamWaitEvent(0, evGh2, 0);
        gru_k<<<(N4 + 255) / 256, 256>>>(gi_, gh_, b_ih, b_hh, sB_, out, sxh_, sxl_, N4);
    }
}

// round 12
// speedup vs baseline: 1.2959x; 1.2102x over previous
#include <cuda_runtime.h>
#include <cuda_bf16.h>
#include <cuda_fp16.h>
#include <cstdint>
#include <math.h>

#define NN 50000
#define CC 128
#define EE 800000
#define NPAD 50048            // 391 * 128
#define RTILES 391

// ---------------- scratch (static device globals; no allocation) ----------
__device__ float g_sA[NN * CC];
__device__ float g_sB[NN * CC];
__device__ float g_gi[NPAD * 3 * CC];
__device__ float g_gh[NPAD * 3 * CC];
__device__ float g_wcomb[384 * CC];
__device__ int   g_cnt[NN];
__device__ int   g_rowptr[NN + 1];
__device__ int   g_perm[EE];
__device__ int   g_bsum[64];

__device__ __half g_sxh[NPAD * CC];     // state, fp16 (GEMM A operand)
__device__ __half g_sph[NPAD * CC];     // prop, fp16 (GEMM A operand)
__device__ __half g_whh_h[384 * CC];    // W_hh hi/lo fp16
__device__ __half g_whh_l[384 * CC];
__device__ __half g_wc_h[384 * CC];     // W_comb hi/lo fp16
__device__ __half g_wc_l[384 * CC];

// ---------------- PTX helpers ----------------------------------------------
__device__ __forceinline__ uint32_t smem_u32(const void* p) {
    uint32_t a;
    asm("{ .reg .u64 t; cvta.to.shared.u64 t, %1; cvt.u32.u64 %0, t; }" : "=r"(a) : "l"(p));
    return a;
}
__device__ __forceinline__ void ldsm4(uint32_t* r, uint32_t addr) {
    asm volatile("ldmatrix.sync.aligned.m8n8.x4.shared.b16 {%0,%1,%2,%3}, [%4];"
                 : "=r"(r[0]), "=r"(r[1]), "=r"(r[2]), "=r"(r[3]) : "r"(addr));
}
__device__ __forceinline__ void mma_f16(float* d, const uint32_t* a,
                                        uint32_t b0, uint32_t b1) {
    asm volatile(
        "mma.sync.aligned.m16n8k16.row.col.f32.f16.f16.f32 "
        "{%0,%1,%2,%3}, {%4,%5,%6,%7}, {%8,%9}, {%0,%1,%2,%3};"
        : "+f"(d[0]), "+f"(d[1]), "+f"(d[2]), "+f"(d[3])
        : "r"(a[0]), "r"(a[1]), "r"(a[2]), "r"(a[3]), "r"(b0), "r"(b1));
}

// ---------------- small utility kernels -----------------------------------
__global__ void zero_int(int* p, int n) {
    int i = blockIdx.x * blockDim.x + threadIdx.x;
    if (i < n) p[i] = 0;
}

__global__ void zero_pad_h(__half* a, __half* b) {
    int i = blockIdx.x * blockDim.x + threadIdx.x;
    int n = (NPAD - NN) * CC;
    if (i < n) {
        int off = NN * CC + i;
        a[off] = __float2half(0.f);
        b[off] = __float2half(0.f);
    }
}

__global__ void count_k(const int* __restrict__ dst, int* __restrict__ cnt) {
    int e = blockIdx.x * blockDim.x + threadIdx.x;
    if (e < EE) {
        int d = dst[e];
        d = min(max(d, 0), NN - 1);
        atomicAdd(&cnt[d], 1);
    }
}

__global__ void scan_block(const int* __restrict__ cnt, int* __restrict__ excl,
                           int* __restrict__ bsum, int n) {
    __shared__ int sm[1024];
    int t = threadIdx.x;
    int g = blockIdx.x * 1024 + t;
    int v = (g < n) ? cnt[g] : 0;
    sm[t] = v;
    __syncthreads();
    for (int off = 1; off < 1024; off <<= 1) {
        int tv = 0;
        if (t >= off) tv = sm[t - off];
        __syncthreads();
        if (t >= off) sm[t] += tv;
        __syncthreads();
    }
    if (g < n) excl[g] = sm[t] - v;
    if (t == 1023) bsum[blockIdx.x] = sm[1023];
}

__global__ void scan_sums(int* bsum, int nb) {
    int run = 0;
    for (int i = 0; i < nb; i++) { int t = bsum[i]; bsum[i] = run; run += t; }
}

__global__ void add_off(int* __restrict__ rowptr, const int* __restrict__ bsum, int n) {
    int g = blockIdx.x * blockDim.x + threadIdx.x;
    if (g < n) rowptr[g] += bsum[g >> 10];
    if (g == 0) rowptr[n] = EE;
}

__global__ void fill_k(const int* __restrict__ src, const int* __restrict__ dst,
                       const int* __restrict__ rowptr, int* __restrict__ cur,
                       int* __restrict__ perm) {
    int e = blockIdx.x * blockDim.x + threadIdx.x;
    if (e < EE) {
        int d = dst[e];
        d = min(max(d, 0), NN - 1);
        int s = src[e];
        s = min(max(s, 0), NN - 1);
        int pos = rowptr[d] + atomicAdd(&cur[d], 1);
        if (pos >= 0 && pos < EE) perm[pos] = s;
    }
}

// ---------------- W_comb = W_ih @ W_lin (fp32, once) -----------------------
__global__ void wcomb_k(const float* __restrict__ W_ih, const float* __restrict__ W_lin,
                        float* __restrict__ W_comb) {
    int i = blockIdx.x;
    int j = threadIdx.x;
    float s = 0.f;
    #pragma unroll 8
    for (int k = 0; k < 128; k++)
        s += W_ih[i * 128 + k] * W_lin[k * 128 + j];
    W_comb[i * 128 + j] = s;
}

// ---------------- fp32 -> fp16 conversions ---------------------------------
__global__ void conv_h(const float* __restrict__ x, __half* __restrict__ o, int n4) {
    int i = blockIdx.x * blockDim.x + threadIdx.x;
    if (i >= n4) return;
    float4 v = ((const float4*)x)[i];
    __half2* o2 = (__half2*)o;
    o2[i * 2 + 0] = __floats2half2_rn(v.x, v.y);
    o2[i * 2 + 1] = __floats2half2_rn(v.z, v.w);
}

__global__ void wsplit(const float* __restrict__ w, __half* __restrict__ hi,
                       __half* __restrict__ lo, int n) {
    int i = blockIdx.x * blockDim.x + threadIdx.x;
    if (i >= n) return;
    float v = w[i];
    __half h = __float2half_rn(v);
    hi[i] = h;
    lo[i] = __float2half_rn(v - __half2float(h));   // subnormal ok
}

// ---------------- 2-term fp16 GEMM (A single, B = Bh + Bl) -----------------
// Y[NPAD, M] = A[NPAD,128] @ ((Bh+Bl)[M,128])^T
// block tile 128x64, 256 threads (8 warps 4x2), warp tile 32x32.
// per warp per kstep: 6 ldsm4, 16 MMAs. smem 69632 B -> 2 CTAs/SM.
// blockIdx.z picks one of two independent GEMM problems (merged launch).
#define LDSB 136
#define ROWB (LDSB * 2)
#define A_T (128 * LDSB)
#define B_T (64 * LDSB)
#define G2_SMEM ((A_T + 2 * B_T) * 2)          // 69632 bytes

__global__ __launch_bounds__(256, 2)
void gemm_h2(const __half* __restrict__ A0, const __half* __restrict__ BH0,
             const __half* __restrict__ BL0, float* __restrict__ Y0,
             const __half* __restrict__ A1, const __half* __restrict__ BH1,
             const __half* __restrict__ BL1, float* __restrict__ Y1, int M) {
    extern __shared__ __half smh[];
    __half* As   = smh;
    __half* Bs_h = smh + A_T;
    __half* Bs_l = smh + A_T + B_T;

    const __half* A  = blockIdx.z ? A1 : A0;
    const __half* Bh = blockIdx.z ? BH1 : BH0;
    const __half* Bl = blockIdx.z ? BL1 : BL0;
    float* Y = blockIdx.z ? Y1 : Y0;

    int row0 = blockIdx.x * 128;
    int col0 = blockIdx.y * 64;
    int t = threadIdx.x;

    {
        const uint4* gA = (const uint4*)(A + (size_t)row0 * 128);
        #pragma unroll
        for (int i = 0; i < 8; i++) {
            int idx = t + i * 256;
            int r = idx >> 4, c = idx & 15;
            ((uint4*)((char*)As + r * ROWB))[c] = gA[idx];
        }
        const uint4* gBh = (const uint4*)(Bh + (size_t)col0 * 128);
        const uint4* gBl = (const uint4*)(Bl + (size_t)col0 * 128);
        #pragma unroll
        for (int i = 0; i < 4; i++) {
            int idx = t + i * 256;
            int r = idx >> 4, c = idx & 15;
            ((uint4*)((char*)Bs_h + r * ROWB))[c] = gBh[idx];
            ((uint4*)((char*)Bs_l + r * ROWB))[c] = gBl[idx];
        }
    }
    __syncthreads();

    int lane = t & 31;
    int wid = t >> 5;
    int wm = wid & 3;
    int wn = wid >> 2;

    uint32_t laneOff = (uint32_t)((lane & 15) * ROWB + (lane >> 4) * 16);
    uint32_t aP = smem_u32(As)   + (uint32_t)(wm * 32) * ROWB + laneOff;
    uint32_t bH = smem_u32(Bs_h) + (uint32_t)(wn * 32) * ROWB + laneOff;
    uint32_t bL = bH + B_T * 2;

    float acc[2][4][4];
    #pragma unroll
    for (int i = 0; i < 2; i++)
        #pragma unroll
        for (int j = 0; j < 4; j++)
            #pragma unroll
            for (int q = 0; q < 4; q++) acc[i][j][q] = 0.f;

    #pragma unroll
    for (int ks = 0; ks < 8; ks++) {
        uint32_t kb = ks * 32;
        uint32_t a0[4], a1[4], p0[4], p1[4];
        ldsm4(a0, aP + kb);
        ldsm4(a1, aP + 16 * ROWB + kb);
        ldsm4(p0, bH + kb);
        ldsm4(p1, bH + 16 * ROWB + kb);
        mma_f16(acc[0][0], a0, p0[0], p0[2]);
        mma_f16(acc[0][1], a0, p0[1], p0[3]);
        mma_f16(acc[0][2], a0, p1[0], p1[2]);
        mma_f16(acc[0][3], a0, p1[1], p1[3]);
        mma_f16(acc[1][0], a1, p0[0], p0[2]);
        mma_f16(acc[1][1], a1, p0[1], p0[3]);
        mma_f16(acc[1][2], a1, p1[0], p1[2]);
        mma_f16(acc[1][3], a1, p1[1], p1[3]);
        uint32_t q0[4], q1[4];
        ldsm4(q0, bL + kb);
        ldsm4(q1, bL + 16 * ROWB + kb);
        mma_f16(acc[0][0], a0, q0[0], q0[2]);
        mma_f16(acc[0][1], a0, q0[1], q0[3]);
        mma_f16(acc[0][2], a0, q1[0], q1[2]);
        mma_f16(acc[0][3], a0, q1[1], q1[3]);
        mma_f16(acc[1][0], a1, q0[0], q0[2]);
        mma_f16(acc[1][1], a1, q0[1], q0[3]);
        mma_f16(acc[1][2], a1, q1[0], q1[2]);
        mma_f16(acc[1][3], a1, q1[1], q1[3]);
    }

    int r = row0 + wm * 32 + (lane >> 2);
    int c = col0 + wn * 32 + (lane & 3) * 2;
    #pragma unroll
    for (int i = 0; i < 2; i++) {
        #pragma unroll
        for (int j = 0; j < 4; j++) {
            float2 v0 = make_float2(acc[i][j][0], acc[i][j][1]);
            float2 v1 = make_float2(acc[i][j][2], acc[i][j][3]);
            *(float2*)&Y[(size_t)(r + i * 16) * M + c + j * 8] = v0;
            *(float2*)&Y[(size_t)(r + i * 16 + 8) * M + c + j * 8] = v1;
        }
    }
}

// ---------------- aggregation (fp32 in, fp16 out) ---------------------------
__global__ void aggregate(const float* __restrict__ st, const int* __restrict__ rowptr,
                          const int* __restrict__ perm, __half* __restrict__ ph) {
    int i = blockIdx.x;
    int c = threadIdx.x;
    int s0 = rowptr[i], s1 = rowptr[i + 1];
    float a0 = 0.f, a1 = 0.f, a2 = 0.f, a3 = 0.f;
    int e = s0;
    for (; e + 3 < s1; e += 4) {
        int p0 = perm[e], p1 = perm[e + 1], p2 = perm[e + 2], p3 = perm[e + 3];
        a0 += st[p0 * 128 + c];
        a1 += st[p1 * 128 + c];
        a2 += st[p2 * 128 + c];
        a3 += st[p3 * 128 + c];
    }
    for (; e < s1; e++) a0 += st[perm[e] * 128 + c];
    float s = (a0 + a1) + (a2 + a3);
    ph[i * 128 + c] = __float2half_rn(s);
}

// ---------------- GRU elementwise (fp32 state out + fp16 copy) --------------
__global__ void gru_k(const float* __restrict__ gi, const float* __restrict__ gh,
                      const float* __restrict__ b_ih, const float* __restrict__ b_hh,
                      const float* __restrict__ h, float* __restrict__ out,
                      __half* __restrict__ oh, int n4) {
    int idx = blockIdx.x * blockDim.x + threadIdx.x;
    if (idx >= n4) return;
    int i = idx >> 5;
    int c4 = (idx & 31) * 4;
    const float4* gir = (const float4*)(gi + (size_t)i * 384 + c4);
    const float4* ghr = (const float4*)(gh + (size_t)i * 384 + c4);
    float4 ir = gir[0],  iz = gir[32],  in_ = gir[64];
    float4 hr = ghr[0],  hz = ghr[32],  hn = ghr[64];
    float4 bir = *(const float4*)(b_ih + c4);
    float4 biz = *(const float4*)(b_ih + 128 + c4);
    float4 bin = *(const float4*)(b_ih + 256 + c4);
    float4 bhr = *(const float4*)(b_hh + c4);
    float4 bhz = *(const float4*)(b_hh + 128 + c4);
    float4 bhn = *(const float4*)(b_hh + 256 + c4);
    float4 hv = *(const float4*)(h + (size_t)i * 128 + c4);

    float o[4];
    #pragma unroll
    for (int q = 0; q < 4; q++) {
        float irq = ((&ir.x)[q] + (&bir.x)[q]) + ((&hr.x)[q] + (&bhr.x)[q]);
        float izq = ((&iz.x)[q] + (&biz.x)[q]) + ((&hz.x)[q] + (&bhz.x)[q]);
        float inq = (&in_.x)[q] + (&bin.x)[q];
        float hnq = (&hn.x)[q] + (&bhn.x)[q];
        float r = 1.f / (1.f + expf(-irq));
        float z = 1.f / (1.f + expf(-izq));
        float nval = tanhf(inq + r * hnq);
        o[q] = (1.f - z) * nval + z * (&hv.x)[q];
    }
    *(float4*)(out + (size_t)i * 128 + c4) = make_float4(o[0], o[1], o[2], o[3]);
    __half2* ohp = (__half2*)(oh + (size_t)i * 128 + c4);
    ohp[0] = __floats2half2_rn(o[0], o[1]);
    ohp[1] = __floats2half2_rn(o[2], o[3]);
}

// ---------------- launcher --------------------------------------------------
extern "C" void kernel_launch(void* const* d_in, const int* in_sizes, int n_in,
                              void* d_out, int out_size) {
    const float* x     = (const float*)d_in[0];
    const int*   ei    = (const int*)d_in[1];
    const float* W_lin = (const float*)d_in[2];
    const float* W_ih  = (const float*)d_in[3];
    const float* W_hh  = (const float*)d_in[4];
    const float* b_ih  = (const float*)d_in[5];
    const float* b_hh  = (const float*)d_in[6];
    float* out = (float*)d_out;

    const int* src = ei;
    const int* dst = ei + EE;

    float *sA_, *sB_, *gi_, *gh_, *wc_;
    int *cnt_, *rp_, *perm_, *bsum_;
    __half *sxh_, *sph_, *whhh_, *whhl_, *wch_, *wcl_;
    cudaGetSymbolAddress((void**)&sA_,   g_sA);
    cudaGetSymbolAddress((void**)&sB_,   g_sB);
    cudaGetSymbolAddress((void**)&gi_,   g_gi);
    cudaGetSymbolAddress((void**)&gh_,   g_gh);
    cudaGetSymbolAddress((void**)&wc_,   g_wcomb);
    cudaGetSymbolAddress((void**)&cnt_,  g_cnt);
    cudaGetSymbolAddress((void**)&rp_,   g_rowptr);
    cudaGetSymbolAddress((void**)&perm_, g_perm);
    cudaGetSymbolAddress((void**)&bsum_, g_bsum);
    cudaGetSymbolAddress((void**)&sxh_,  g_sxh);
    cudaGetSymbolAddress((void**)&sph_,  g_sph);
    cudaGetSymbolAddress((void**)&whhh_, g_whh_h);
    cudaGetSymbolAddress((void**)&whhl_, g_whh_l);
    cudaGetSymbolAddress((void**)&wch_,  g_wc_h);
    cudaGetSymbolAddress((void**)&wcl_,  g_wc_l);

    cudaFuncSetAttribute(gemm_h2, cudaFuncAttributeMaxDynamicSharedMemorySize, G2_SMEM);

    cudaStream_t s2;
    cudaStreamCreateWithFlags(&s2, cudaStreamNonBlocking);
    cudaEvent_t evRoot, evCSR;
    cudaEventCreateWithFlags(&evRoot, cudaEventDisableTiming);
    cudaEventCreateWithFlags(&evCSR,  cudaEventDisableTiming);

    const int NB_SCAN = (NN + 1023) / 1024;
    const int N4 = NN * CC / 4;
    const dim3 gg1(RTILES, 6, 1);      // single GEMM
    const dim3 gg2(RTILES, 6, 2);      // merged gi+gh

    // ---- prologue; gemm_h2 = my launch #4 (ncu -s 5 -c 1 lands there) ----
    conv_h<<<(N4 + 255) / 256, 256>>>(x, sxh_, N4);                                   // 1
    wsplit<<<(384 * CC + 255) / 256, 256>>>(W_hh, whhh_, whhl_, 384 * CC);            // 2
    zero_pad_h<<<((NPAD - NN) * CC + 255) / 256, 256>>>(sxh_, sph_);                  // 3
    gemm_h2<<<gg1, 256, G2_SMEM>>>(sxh_, whhh_, whhl_, gh_,                           // 4 (profiled)
                                   sxh_, whhh_, whhl_, gh_, 384);
    wcomb_k<<<384, 128>>>(W_ih, W_lin, wc_);
    wsplit<<<(384 * CC + 255) / 256, 256>>>(wc_, wch_, wcl_, 384 * CC);

    // ---- CSR build on side stream (overlaps prologue) ----
    cudaEventRecord(evRoot, 0);
    cudaStreamWaitEvent(s2, evRoot, 0);
    zero_int <<<(NN + 255) / 256, 256, 0, s2>>>(cnt_, NN);
    count_k  <<<(EE + 255) / 256, 256, 0, s2>>>(dst, cnt_);
    scan_block<<<NB_SCAN, 1024, 0, s2>>>(cnt_, rp_, bsum_, NN);
    scan_sums <<<1, 1, 0, s2>>>(bsum_, NB_SCAN);
    add_off   <<<(NN + 255) / 256, 256, 0, s2>>>(rp_, bsum_, NN);
    zero_int  <<<(NN + 255) / 256, 256, 0, s2>>>(cnt_, NN);
    fill_k    <<<(EE + 255) / 256, 256, 0, s2>>>(src, dst, rp_, cnt_, perm_);
    cudaEventRecord(evCSR, s2);
    cudaStreamWaitEvent(0, evCSR, 0);

    // ---- step 0 (gh computed at launch 4) ----
    aggregate<<<NN, 128>>>(x, rp_, perm_, sph_);
    gemm_h2<<<gg1, 256, G2_SMEM>>>(sph_, wch_, wcl_, gi_,
                                   sph_, wch_, wcl_, gi_, 384);
    gru_k<<<(N4 + 255) / 256, 256>>>(gi_, gh_, b_ih, b_hh, x, sA_, sxh_, N4);

    // ---- steps 1, 2: merged gi+gh GEMM ----
    aggregate<<<NN, 128>>>(sA_, rp_, perm_, sph_);
    gemm_h2<<<gg2, 256, G2_SMEM>>>(sph_, wch_, wcl_, gi_,
                                   sxh_, whhh_, whhl_, gh_, 384);
    gru_k<<<(N4 + 255) / 256, 256>>>(gi_, gh_, b_ih, b_hh, sA_, sB_, sxh_, N4);

    aggregate<<<NN, 128>>>(sB_, rp_, perm_, sph_);
    gemm_h2<<<gg2, 256, G2_SMEM>>>(sph_, wch_, wcl_, gi_,
                                   sxh_, whhh_, whhl_, gh_, 384);
    gru_k<<<(N4 + 255) / 256, 256>>>(gi_, gh_, b_ih, b_hh, sB_, out, sxh_, N4);
}

// round 13
// speedup vs baseline: 1.4420x; 1.1128x over previous
#include <cuda_runtime.h>
#include <cuda_bf16.h>
#include <cuda_fp16.h>
#include <cstdint>
#include <math.h>

#define NN 50000
#define CC 128
#define EE 800000
#define NPAD 50048            // 391 * 128
#define RTILES 391

// ---------------- scratch (static device globals; no allocation) ----------
__device__ float g_sA[NN * CC];
__device__ float g_sB[NN * CC];
__device__ float g_gi[NPAD * 3 * CC];
__device__ float g_gh[NPAD * 3 * CC];
__device__ float g_wcomb[384 * CC];
__device__ int   g_cnt[NN];
__device__ int   g_rowptr[NN + 1];
__device__ int   g_perm[EE];
__device__ int   g_bsum[64];

__device__ __half g_sxh[NPAD * CC];     // state, fp16 (GEMM A operand + gather src)
__device__ __half g_sph[NPAD * CC];     // prop, fp16 (GEMM A operand)
__device__ __half g_whh_h[384 * CC];    // W_hh hi/lo fp16
__device__ __half g_whh_l[384 * CC];
__device__ __half g_wc_h[384 * CC];     // W_comb hi/lo fp16
__device__ __half g_wc_l[384 * CC];

// ---------------- PTX helpers ----------------------------------------------
__device__ __forceinline__ uint32_t smem_u32(const void* p) {
    uint32_t a;
    asm("{ .reg .u64 t; cvta.to.shared.u64 t, %1; cvt.u32.u64 %0, t; }" : "=r"(a) : "l"(p));
    return a;
}
__device__ __forceinline__ void ldsm4(uint32_t* r, uint32_t addr) {
    asm volatile("ldmatrix.sync.aligned.m8n8.x4.shared.b16 {%0,%1,%2,%3}, [%4];"
                 : "=r"(r[0]), "=r"(r[1]), "=r"(r[2]), "=r"(r[3]) : "r"(addr));
}
__device__ __forceinline__ void mma_f16(float* d, const uint32_t* a,
                                        uint32_t b0, uint32_t b1) {
    asm volatile(
        "mma.sync.aligned.m16n8k16.row.col.f32.f16.f16.f32 "
        "{%0,%1,%2,%3}, {%4,%5,%6,%7}, {%8,%9}, {%0,%1,%2,%3};"
        : "+f"(d[0]), "+f"(d[1]), "+f"(d[2]), "+f"(d[3])
        : "r"(a[0]), "r"(a[1]), "r"(a[2]), "r"(a[3]), "r"(b0), "r"(b1));
}

// ---------------- small utility kernels -----------------------------------
__global__ void zero_int(int* p, int n) {
    int i = blockIdx.x * blockDim.x + threadIdx.x;
    if (i < n) p[i] = 0;
}

__global__ void zero_pad_h(__half* a, __half* b) {
    int i = blockIdx.x * blockDim.x + threadIdx.x;
    int n = (NPAD - NN) * CC;
    if (i < n) {
        int off = NN * CC + i;
        a[off] = __float2half(0.f);
        b[off] = __float2half(0.f);
    }
}

__global__ void count_k(const int* __restrict__ dst, int* __restrict__ cnt) {
    int e = blockIdx.x * blockDim.x + threadIdx.x;
    if (e < EE) {
        int d = dst[e];
        d = min(max(d, 0), NN - 1);
        atomicAdd(&cnt[d], 1);
    }
}

__global__ void scan_block(const int* __restrict__ cnt, int* __restrict__ excl,
                           int* __restrict__ bsum, int n) {
    __shared__ int sm[1024];
    int t = threadIdx.x;
    int g = blockIdx.x * 1024 + t;
    int v = (g < n) ? cnt[g] : 0;
    sm[t] = v;
    __syncthreads();
    for (int off = 1; off < 1024; off <<= 1) {
        int tv = 0;
        if (t >= off) tv = sm[t - off];
        __syncthreads();
        if (t >= off) sm[t] += tv;
        __syncthreads();
    }
    if (g < n) excl[g] = sm[t] - v;
    if (t == 1023) bsum[blockIdx.x] = sm[1023];
}

__global__ void scan_sums(int* bsum, int nb) {
    int run = 0;
    for (int i = 0; i < nb; i++) { int t = bsum[i]; bsum[i] = run; run += t; }
}

__global__ void add_off(int* __restrict__ rowptr, const int* __restrict__ bsum, int n) {
    int g = blockIdx.x * blockDim.x + threadIdx.x;
    if (g < n) rowptr[g] += bsum[g >> 10];
    if (g == 0) rowptr[n] = EE;
}

__global__ void fill_k(const int* __restrict__ src, const int* __restrict__ dst,
                       const int* __restrict__ rowptr, int* __restrict__ cur,
                       int* __restrict__ perm) {
    int e = blockIdx.x * blockDim.x + threadIdx.x;
    if (e < EE) {
        int d = dst[e];
        d = min(max(d, 0), NN - 1);
        int s = src[e];
        s = min(max(s, 0), NN - 1);
        int pos = rowptr[d] + atomicAdd(&cur[d], 1);
        if (pos >= 0 && pos < EE) perm[pos] = s;
    }
}

// ---------------- W_comb = W_ih @ W_lin (fp32, once) -----------------------
__global__ void wcomb_k(const float* __restrict__ W_ih, const float* __restrict__ W_lin,
                        float* __restrict__ W_comb) {
    int i = blockIdx.x;
    int j = threadIdx.x;
    float s = 0.f;
    #pragma unroll 8
    for (int k = 0; k < 128; k++)
        s += W_ih[i * 128 + k] * W_lin[k * 128 + j];
    W_comb[i * 128 + j] = s;
}

// ---------------- fp32 -> fp16 conversions ---------------------------------
__global__ void conv_h(const float* __restrict__ x, __half* __restrict__ o, int n4) {
    int i = blockIdx.x * blockDim.x + threadIdx.x;
    if (i >= n4) return;
    float4 v = ((const float4*)x)[i];
    __half2* o2 = (__half2*)o;
    o2[i * 2 + 0] = __floats2half2_rn(v.x, v.y);
    o2[i * 2 + 1] = __floats2half2_rn(v.z, v.w);
}

__global__ void wsplit(const float* __restrict__ w, __half* __restrict__ hi,
                       __half* __restrict__ lo, int n) {
    int i = blockIdx.x * blockDim.x + threadIdx.x;
    if (i >= n) return;
    float v = w[i];
    __half h = __float2half_rn(v);
    hi[i] = h;
    lo[i] = __float2half_rn(v - __half2float(h));   // subnormal ok
}

// ---------------- 2-term fp16 GEMM (A single, B = Bh + Bl) -----------------
#define LDSB 136
#define ROWB (LDSB * 2)
#define A_T (128 * LDSB)
#define B_T (64 * LDSB)
#define G2_SMEM ((A_T + 2 * B_T) * 2)          // 69632 bytes

__global__ __launch_bounds__(256, 2)
void gemm_h2(const __half* __restrict__ A0, const __half* __restrict__ BH0,
             const __half* __restrict__ BL0, float* __restrict__ Y0,
             const __half* __restrict__ A1, const __half* __restrict__ BH1,
             const __half* __restrict__ BL1, float* __restrict__ Y1, int M) {
    extern __shared__ __half smh[];
    __half* As   = smh;
    __half* Bs_h = smh + A_T;
    __half* Bs_l = smh + A_T + B_T;

    const __half* A  = blockIdx.z ? A1 : A0;
    const __half* Bh = blockIdx.z ? BH1 : BH0;
    const __half* Bl = blockIdx.z ? BL1 : BL0;
    float* Y = blockIdx.z ? Y1 : Y0;

    int row0 = blockIdx.x * 128;
    int col0 = blockIdx.y * 64;
    int t = threadIdx.x;

    {
        const uint4* gA = (const uint4*)(A + (size_t)row0 * 128);
        #pragma unroll
        for (int i = 0; i < 8; i++) {
            int idx = t + i * 256;
            int r = idx >> 4, c = idx & 15;
            ((uint4*)((char*)As + r * ROWB))[c] = gA[idx];
        }
        const uint4* gBh = (const uint4*)(Bh + (size_t)col0 * 128);
        const uint4* gBl = (const uint4*)(Bl + (size_t)col0 * 128);
        #pragma unroll
        for (int i = 0; i < 4; i++) {
            int idx = t + i * 256;
            int r = idx >> 4, c = idx & 15;
            ((uint4*)((char*)Bs_h + r * ROWB))[c] = gBh[idx];
            ((uint4*)((char*)Bs_l + r * ROWB))[c] = gBl[idx];
        }
    }
    __syncthreads();

    int lane = t & 31;
    int wid = t >> 5;
    int wm = wid & 3;
    int wn = wid >> 2;

    uint32_t laneOff = (uint32_t)((lane & 15) * ROWB + (lane >> 4) * 16);
    uint32_t aP = smem_u32(As)   + (uint32_t)(wm * 32) * ROWB + laneOff;
    uint32_t bH = smem_u32(Bs_h) + (uint32_t)(wn * 32) * ROWB + laneOff;
    uint32_t bL = bH + B_T * 2;

    float acc[2][4][4];
    #pragma unroll
    for (int i = 0; i < 2; i++)
        #pragma unroll
        for (int j = 0; j < 4; j++)
            #pragma unroll
            for (int q = 0; q < 4; q++) acc[i][j][q] = 0.f;

    #pragma unroll
    for (int ks = 0; ks < 8; ks++) {
        uint32_t kb = ks * 32;
        uint32_t a0[4], a1[4], p0[4], p1[4];
        ldsm4(a0, aP + kb);
        ldsm4(a1, aP + 16 * ROWB + kb);
        ldsm4(p0, bH + kb);
        ldsm4(p1, bH + 16 * ROWB + kb);
        mma_f16(acc[0][0], a0, p0[0], p0[2]);
        mma_f16(acc[0][1], a0, p0[1], p0[3]);
        mma_f16(acc[0][2], a0, p1[0], p1[2]);
        mma_f16(acc[0][3], a0, p1[1], p1[3]);
        mma_f16(acc[1][0], a1, p0[0], p0[2]);
        mma_f16(acc[1][1], a1, p0[1], p0[3]);
        mma_f16(acc[1][2], a1, p1[0], p1[2]);
        mma_f16(acc[1][3], a1, p1[1], p1[3]);
        uint32_t q0[4], q1[4];
        ldsm4(q0, bL + kb);
        ldsm4(q1, bL + 16 * ROWB + kb);
        mma_f16(acc[0][0], a0, q0[0], q0[2]);
        mma_f16(acc[0][1], a0, q0[1], q0[3]);
        mma_f16(acc[0][2], a0, q1[0], q1[2]);
        mma_f16(acc[0][3], a0, q1[1], q1[3]);
        mma_f16(acc[1][0], a1, q0[0], q0[2]);
        mma_f16(acc[1][1], a1, q0[1], q0[3]);
        mma_f16(acc[1][2], a1, q1[0], q1[2]);
        mma_f16(acc[1][3], a1, q1[1], q1[3]);
    }

    int r = row0 + wm * 32 + (lane >> 2);
    int c = col0 + wn * 32 + (lane & 3) * 2;
    #pragma unroll
    for (int i = 0; i < 2; i++) {
        #pragma unroll
        for (int j = 0; j < 4; j++) {
            float2 v0 = make_float2(acc[i][j][0], acc[i][j][1]);
            float2 v1 = make_float2(acc[i][j][2], acc[i][j][3]);
            *(float2*)&Y[(size_t)(r + i * 16) * M + c + j * 8] = v0;
            *(float2*)&Y[(size_t)(r + i * 16 + 8) * M + c + j * 8] = v1;
        }
    }
}

// ---------------- aggregation: gather fp16 state, fp32 accum, fp16 out -----
// 2 nodes per 128-thread block; each thread owns a half2 (channels 2c,2c+1).
__global__ __launch_bounds__(128)
void aggregate_h(const __half* __restrict__ st, const int* __restrict__ rowptr,
                 const int* __restrict__ perm, __half* __restrict__ ph) {
    int i = blockIdx.x * 2 + (threadIdx.x >> 6);
    int c2 = threadIdx.x & 63;             // half2 index within row (64 per row)
    if (i >= NN) return;
    const __half2* st2 = (const __half2*)st;
    int s0 = rowptr[i], s1 = rowptr[i + 1];
    float ax0 = 0.f, ay0 = 0.f, ax1 = 0.f, ay1 = 0.f;
    int e = s0;
    for (; e + 1 < s1; e += 2) {
        int p0 = perm[e], p1 = perm[e + 1];
        float2 f0 = __half22float2(st2[p0 * 64 + c2]);
        float2 f1 = __half22float2(st2[p1 * 64 + c2]);
        ax0 += f0.x; ay0 += f0.y;
        ax1 += f1.x; ay1 += f1.y;
    }
    if (e < s1) {
        float2 f0 = __half22float2(st2[perm[e] * 64 + c2]);
        ax0 += f0.x; ay0 += f0.y;
    }
    ((__half2*)ph)[i * 64 + c2] = __floats2half2_rn(ax0 + ax1, ay0 + ay1);
}

// ---------------- GRU elementwise (fp32 state out + fp16 copy) --------------
__global__ void gru_k(const float* __restrict__ gi, const float* __restrict__ gh,
                      const float* __restrict__ b_ih, const float* __restrict__ b_hh,
                      const float* __restrict__ h, float* __restrict__ out,
                      __half* __restrict__ oh, int n4) {
    int idx = blockIdx.x * blockDim.x + threadIdx.x;
    if (idx >= n4) return;
    int i = idx >> 5;
    int c4 = (idx & 31) * 4;
    const float4* gir = (const float4*)(gi + (size_t)i * 384 + c4);
    const float4* ghr = (const float4*)(gh + (size_t)i * 384 + c4);
    float4 ir = gir[0],  iz = gir[32],  in_ = gir[64];
    float4 hr = ghr[0],  hz = ghr[32],  hn = ghr[64];
    float4 bir = *(const float4*)(b_ih + c4);
    float4 biz = *(const float4*)(b_ih + 128 + c4);
    float4 bin = *(const float4*)(b_ih + 256 + c4);
    float4 bhr = *(const float4*)(b_hh + c4);
    float4 bhz = *(const float4*)(b_hh + 128 + c4);
    float4 bhn = *(const float4*)(b_hh + 256 + c4);
    float4 hv = *(const float4*)(h + (size_t)i * 128 + c4);

    float o[4];
    #pragma unroll
    for (int q = 0; q < 4; q++) {
        float irq = ((&ir.x)[q] + (&bir.x)[q]) + ((&hr.x)[q] + (&bhr.x)[q]);
        float izq = ((&iz.x)[q] + (&biz.x)[q]) + ((&hz.x)[q] + (&bhz.x)[q]);
        float inq = (&in_.x)[q] + (&bin.x)[q];
        float hnq = (&hn.x)[q] + (&bhn.x)[q];
        float r = 1.f / (1.f + expf(-irq));
        float z = 1.f / (1.f + expf(-izq));
        float nval = tanhf(inq + r * hnq);
        o[q] = (1.f - z) * nval + z * (&hv.x)[q];
    }
    *(float4*)(out + (size_t)i * 128 + c4) = make_float4(o[0], o[1], o[2], o[3]);
    __half2* ohp = (__half2*)(oh + (size_t)i * 128 + c4);
    ohp[0] = __floats2half2_rn(o[0], o[1]);
    ohp[1] = __floats2half2_rn(o[2], o[3]);
}

// ---------------- launcher --------------------------------------------------
extern "C" void kernel_launch(void* const* d_in, const int* in_sizes, int n_in,
                              void* d_out, int out_size) {
    const float* x     = (const float*)d_in[0];
    const int*   ei    = (const int*)d_in[1];
    const float* W_lin = (const float*)d_in[2];
    const float* W_ih  = (const float*)d_in[3];
    const float* W_hh  = (const float*)d_in[4];
    const float* b_ih  = (const float*)d_in[5];
    const float* b_hh  = (const float*)d_in[6];
    float* out = (float*)d_out;

    const int* src = ei;
    const int* dst = ei + EE;

    float *sA_, *sB_, *gi_, *gh_, *wc_;
    int *cnt_, *rp_, *perm_, *bsum_;
    __half *sxh_, *sph_, *whhh_, *whhl_, *wch_, *wcl_;
    cudaGetSymbolAddress((void**)&sA_,   g_sA);
    cudaGetSymbolAddress((void**)&sB_,   g_sB);
    cudaGetSymbolAddress((void**)&gi_,   g_gi);
    cudaGetSymbolAddress((void**)&gh_,   g_gh);
    cudaGetSymbolAddress((void**)&wc_,   g_wcomb);
    cudaGetSymbolAddress((void**)&cnt_,  g_cnt);
    cudaGetSymbolAddress((void**)&rp_,   g_rowptr);
    cudaGetSymbolAddress((void**)&perm_, g_perm);
    cudaGetSymbolAddress((void**)&bsum_, g_bsum);
    cudaGetSymbolAddress((void**)&sxh_,  g_sxh);
    cudaGetSymbolAddress((void**)&sph_,  g_sph);
    cudaGetSymbolAddress((void**)&whhh_, g_whh_h);
    cudaGetSymbolAddress((void**)&whhl_, g_whh_l);
    cudaGetSymbolAddress((void**)&wch_,  g_wc_h);
    cudaGetSymbolAddress((void**)&wcl_,  g_wc_l);

    cudaFuncSetAttribute(gemm_h2, cudaFuncAttributeMaxDynamicSharedMemorySize, G2_SMEM);

    cudaStream_t s2;
    cudaStreamCreateWithFlags(&s2, cudaStreamNonBlocking);
    cudaEvent_t evRoot, evCSR;
    cudaEventCreateWithFlags(&evRoot, cudaEventDisableTiming);
    cudaEventCreateWithFlags(&evCSR,  cudaEventDisableTiming);

    const int NB_SCAN = (NN + 1023) / 1024;
    const int N4 = NN * CC / 4;
    const int NAGG = (NN + 1) / 2;
    const dim3 gg1(RTILES, 6, 1);
    const dim3 gg2(RTILES, 6, 2);

    // ---- prologue; gemm_h2 = my launch #4 (ncu -s 5 -c 1 lands there) ----
    conv_h<<<(N4 + 255) / 256, 256>>>(x, sxh_, N4);                                   // 1
    wsplit<<<(384 * CC + 255) / 256, 256>>>(W_hh, whhh_, whhl_, 384 * CC);            // 2
    zero_pad_h<<<((NPAD - NN) * CC + 255) / 256, 256>>>(sxh_, sph_);                  // 3
    gemm_h2<<<gg1, 256, G2_SMEM>>>(sxh_, whhh_, whhl_, gh_,                           // 4 (profiled)
                                   sxh_, whhh_, whhl_, gh_, 384);
    wcomb_k<<<384, 128>>>(W_ih, W_lin, wc_);
    wsplit<<<(384 * CC + 255) / 256, 256>>>(wc_, wch_, wcl_, 384 * CC);

    // ---- CSR build on side stream (overlaps prologue) ----
    cudaEventRecord(evRoot, 0);
    cudaStreamWaitEvent(s2, evRoot, 0);
    zero_int <<<(NN + 255) / 256, 256, 0, s2>>>(cnt_, NN);
    count_k  <<<(EE + 255) / 256, 256, 0, s2>>>(dst, cnt_);
    scan_block<<<NB_SCAN, 1024, 0, s2>>>(cnt_, rp_, bsum_, NN);
    scan_sums <<<1, 1, 0, s2>>>(bsum_, NB_SCAN);
    add_off   <<<(NN + 255) / 256, 256, 0, s2>>>(rp_, bsum_, NN);
    zero_int  <<<(NN + 255) / 256, 256, 0, s2>>>(cnt_, NN);
    fill_k    <<<(EE + 255) / 256, 256, 0, s2>>>(src, dst, rp_, cnt_, perm_);
    cudaEventRecord(evCSR, s2);
    cudaStreamWaitEvent(0, evCSR, 0);

    // ---- step 0 (gh computed at launch 4); gather fp16 state ----
    aggregate_h<<<NAGG, 128>>>(sxh_, rp_, perm_, sph_);
    gemm_h2<<<gg1, 256, G2_SMEM>>>(sph_, wch_, wcl_, gi_,
                                   sph_, wch_, wcl_, gi_, 384);
    gru_k<<<(N4 + 255) / 256, 256>>>(gi_, gh_, b_ih, b_hh, x, sA_, sxh_, N4);

    // ---- steps 1, 2: merged gi+gh GEMM ----
    aggregate_h<<<NAGG, 128>>>(sxh_, rp_, perm_, sph_);
    gemm_h2<<<gg2, 256, G2_SMEM>>>(sph_, wch_, wcl_, gi_,
                                   sxh_, whhh_, whhl_, gh_, 384);
    gru_k<<<(N4 + 255) / 256, 256>>>(gi_, gh_, b_ih, b_hh, sA_, sB_, sxh_, N4);

    aggregate_h<<<NAGG, 128>>>(sxh_, rp_, perm_, sph_);
    gemm_h2<<<gg2, 256, G2_SMEM>>>(sph_, wch_, wcl_, gi_,
                                   sxh_, whhh_, whhl_, gh_, 384);
    gru_k<<<(N4 + 255) / 256, 256>>>(gi_, gh_, b_ih, b_hh, sB_, out, sxh_, N4);
}

// round 14
// speedup vs baseline: 1.5982x; 1.1083x over previous
#include <cuda_runtime.h>
#include <cuda_bf16.h>
#include <cuda_fp16.h>
#include <cstdint>
#include <math.h>

#define NN 50000
#define CC 128
#define EE 800000
#define NPAD 50048            // 391 * 128
#define RTILES 391

// ---------------- scratch (static device globals; no allocation) ----------
__device__ float g_sA[NN * CC];
__device__ float g_sB[NN * CC];
__device__ __half g_gi[NPAD * 3 * CC];   // input gates, fp16
__device__ __half g_gh[NPAD * 3 * CC];   // hidden gates, fp16
__device__ float g_wcomb[384 * CC];
__device__ int   g_cnt[NN];
__device__ int   g_rowptr[NN + 1];
__device__ int   g_perm[EE];
__device__ int   g_bsum[64];

__device__ __half g_sxh[NPAD * CC];     // state, fp16 (GEMM A operand + gather src)
__device__ __half g_sph[NPAD * CC];     // prop, fp16 (GEMM A operand)
__device__ __half g_whh_h[384 * CC];    // W_hh hi/lo fp16
__device__ __half g_whh_l[384 * CC];
__device__ __half g_wc_h[384 * CC];     // W_comb hi/lo fp16
__device__ __half g_wc_l[384 * CC];

// ---------------- PTX helpers ----------------------------------------------
__device__ __forceinline__ uint32_t smem_u32(const void* p) {
    uint32_t a;
    asm("{ .reg .u64 t; cvta.to.shared.u64 t, %1; cvt.u32.u64 %0, t; }" : "=r"(a) : "l"(p));
    return a;
}
__device__ __forceinline__ void ldsm4(uint32_t* r, uint32_t addr) {
    asm volatile("ldmatrix.sync.aligned.m8n8.x4.shared.b16 {%0,%1,%2,%3}, [%4];"
                 : "=r"(r[0]), "=r"(r[1]), "=r"(r[2]), "=r"(r[3]) : "r"(addr));
}
__device__ __forceinline__ void mma_f16(float* d, const uint32_t* a,
                                        uint32_t b0, uint32_t b1) {
    asm volatile(
        "mma.sync.aligned.m16n8k16.row.col.f32.f16.f16.f32 "
        "{%0,%1,%2,%3}, {%4,%5,%6,%7}, {%8,%9}, {%0,%1,%2,%3};"
        : "+f"(d[0]), "+f"(d[1]), "+f"(d[2]), "+f"(d[3])
        : "r"(a[0]), "r"(a[1]), "r"(a[2]), "r"(a[3]), "r"(b0), "r"(b1));
}

// ---------------- small utility kernels -----------------------------------
__global__ void zero_int(int* p, int n) {
    int i = blockIdx.x * blockDim.x + threadIdx.x;
    if (i < n) p[i] = 0;
}

__global__ void zero_pad_h(__half* a, __half* b) {
    int i = blockIdx.x * blockDim.x + threadIdx.x;
    int n = (NPAD - NN) * CC;
    if (i < n) {
        int off = NN * CC + i;
        a[off] = __float2half(0.f);
        b[off] = __float2half(0.f);
    }
}

__global__ void count_k(const int* __restrict__ dst, int* __restrict__ cnt) {
    int e = blockIdx.x * blockDim.x + threadIdx.x;
    if (e < EE) {
        int d = dst[e];
        d = min(max(d, 0), NN - 1);
        atomicAdd(&cnt[d], 1);
    }
}

__global__ void scan_block(const int* __restrict__ cnt, int* __restrict__ excl,
                           int* __restrict__ bsum, int n) {
    __shared__ int sm[1024];
    int t = threadIdx.x;
    int g = blockIdx.x * 1024 + t;
    int v = (g < n) ? cnt[g] : 0;
    sm[t] = v;
    __syncthreads();
    for (int off = 1; off < 1024; off <<= 1) {
        int tv = 0;
        if (t >= off) tv = sm[t - off];
        __syncthreads();
        if (t >= off) sm[t] += tv;
        __syncthreads();
    }
    if (g < n) excl[g] = sm[t] - v;
    if (t == 1023) bsum[blockIdx.x] = sm[1023];
}

__global__ void scan_sums(int* bsum, int nb) {
    int run = 0;
    for (int i = 0; i < nb; i++) { int t = bsum[i]; bsum[i] = run; run += t; }
}

__global__ void add_off(int* __restrict__ rowptr, const int* __restrict__ bsum, int n) {
    int g = blockIdx.x * blockDim.x + threadIdx.x;
    if (g < n) rowptr[g] += bsum[g >> 10];
    if (g == 0) rowptr[n] = EE;
}

__global__ void fill_k(const int* __restrict__ src, const int* __restrict__ dst,
                       const int* __restrict__ rowptr, int* __restrict__ cur,
                       int* __restrict__ perm) {
    int e = blockIdx.x * blockDim.x + threadIdx.x;
    if (e < EE) {
        int d = dst[e];
        d = min(max(d, 0), NN - 1);
        int s = src[e];
        s = min(max(s, 0), NN - 1);
        int pos = rowptr[d] + atomicAdd(&cur[d], 1);
        if (pos >= 0 && pos < EE) perm[pos] = s;
    }
}

// ---------------- W_comb = W_ih @ W_lin (fp32, once) -----------------------
__global__ void wcomb_k(const float* __restrict__ W_ih, const float* __restrict__ W_lin,
                        float* __restrict__ W_comb) {
    int i = blockIdx.x;
    int j = threadIdx.x;
    float s = 0.f;
    #pragma unroll 8
    for (int k = 0; k < 128; k++)
        s += W_ih[i * 128 + k] * W_lin[k * 128 + j];
    W_comb[i * 128 + j] = s;
}

// ---------------- fp32 -> fp16 conversions ---------------------------------
__global__ void conv_h(const float* __restrict__ x, __half* __restrict__ o, int n4) {
    int i = blockIdx.x * blockDim.x + threadIdx.x;
    if (i >= n4) return;
    float4 v = ((const float4*)x)[i];
    __half2* o2 = (__half2*)o;
    o2[i * 2 + 0] = __floats2half2_rn(v.x, v.y);
    o2[i * 2 + 1] = __floats2half2_rn(v.z, v.w);
}

__global__ void wsplit(const float* __restrict__ w, __half* __restrict__ hi,
                       __half* __restrict__ lo, int n) {
    int i = blockIdx.x * blockDim.x + threadIdx.x;
    if (i >= n) return;
    float v = w[i];
    __half h = __float2half_rn(v);
    hi[i] = h;
    lo[i] = __float2half_rn(v - __half2float(h));   // subnormal ok
}

// ---------------- 2-term fp16 GEMM (A single, B = Bh + Bl), fp16 out -------
#define LDSB 136
#define ROWB (LDSB * 2)
#define A_T (128 * LDSB)
#define B_T (64 * LDSB)
#define G2_SMEM ((A_T + 2 * B_T) * 2)          // 69632 bytes

__global__ __launch_bounds__(256, 2)
void gemm_h2(const __half* __restrict__ A0, const __half* __restrict__ BH0,
             const __half* __restrict__ BL0, __half* __restrict__ Y0,
             const __half* __restrict__ A1, const __half* __restrict__ BH1,
             const __half* __restrict__ BL1, __half* __restrict__ Y1, int M) {
    extern __shared__ __half smh[];
    __half* As   = smh;
    __half* Bs_h = smh + A_T;
    __half* Bs_l = smh + A_T + B_T;

    const __half* A  = blockIdx.z ? A1 : A0;
    const __half* Bh = blockIdx.z ? BH1 : BH0;
    const __half* Bl = blockIdx.z ? BL1 : BL0;
    __half* Y = blockIdx.z ? Y1 : Y0;

    int row0 = blockIdx.x * 128;
    int col0 = blockIdx.y * 64;
    int t = threadIdx.x;

    {
        const uint4* gA = (const uint4*)(A + (size_t)row0 * 128);
        #pragma unroll
        for (int i = 0; i < 8; i++) {
            int idx = t + i * 256;
            int r = idx >> 4, c = idx & 15;
            ((uint4*)((char*)As + r * ROWB))[c] = gA[idx];
        }
        const uint4* gBh = (const uint4*)(Bh + (size_t)col0 * 128);
        const uint4* gBl = (const uint4*)(Bl + (size_t)col0 * 128);
        #pragma unroll
        for (int i = 0; i < 4; i++) {
            int idx = t + i * 256;
            int r = idx >> 4, c = idx & 15;
            ((uint4*)((char*)Bs_h + r * ROWB))[c] = gBh[idx];
            ((uint4*)((char*)Bs_l + r * ROWB))[c] = gBl[idx];
        }
    }
    __syncthreads();

    int lane = t & 31;
    int wid = t >> 5;
    int wm = wid & 3;
    int wn = wid >> 2;

    uint32_t laneOff = (uint32_t)((lane & 15) * ROWB + (lane >> 4) * 16);
    uint32_t aP = smem_u32(As)   + (uint32_t)(wm * 32) * ROWB + laneOff;
    uint32_t bH = smem_u32(Bs_h) + (uint32_t)(wn * 32) * ROWB + laneOff;
    uint32_t bL = bH + B_T * 2;

    float acc[2][4][4];
    #pragma unroll
    for (int i = 0; i < 2; i++)
        #pragma unroll
        for (int j = 0; j < 4; j++)
            #pragma unroll
            for (int q = 0; q < 4; q++) acc[i][j][q] = 0.f;

    #pragma unroll
    for (int ks = 0; ks < 8; ks++) {
        uint32_t kb = ks * 32;
        uint32_t a0[4], a1[4], p0[4], p1[4];
        ldsm4(a0, aP + kb);
        ldsm4(a1, aP + 16 * ROWB + kb);
        ldsm4(p0, bH + kb);
        ldsm4(p1, bH + 16 * ROWB + kb);
        mma_f16(acc[0][0], a0, p0[0], p0[2]);
        mma_f16(acc[0][1], a0, p0[1], p0[3]);
        mma_f16(acc[0][2], a0, p1[0], p1[2]);
        mma_f16(acc[0][3], a0, p1[1], p1[3]);
        mma_f16(acc[1][0], a1, p0[0], p0[2]);
        mma_f16(acc[1][1], a1, p0[1], p0[3]);
        mma_f16(acc[1][2], a1, p1[0], p1[2]);
        mma_f16(acc[1][3], a1, p1[1], p1[3]);
        uint32_t q0[4], q1[4];
        ldsm4(q0, bL + kb);
        ldsm4(q1, bL + 16 * ROWB + kb);
        mma_f16(acc[0][0], a0, q0[0], q0[2]);
        mma_f16(acc[0][1], a0, q0[1], q0[3]);
        mma_f16(acc[0][2], a0, q1[0], q1[2]);
        mma_f16(acc[0][3], a0, q1[1], q1[3]);
        mma_f16(acc[1][0], a1, q0[0], q0[2]);
        mma_f16(acc[1][1], a1, q0[1], q0[3]);
        mma_f16(acc[1][2], a1, q1[0], q1[2]);
        mma_f16(acc[1][3], a1, q1[1], q1[3]);
    }

    int r = row0 + wm * 32 + (lane >> 2);
    int c = col0 + wn * 32 + (lane & 3) * 2;
    #pragma unroll
    for (int i = 0; i < 2; i++) {
        #pragma unroll
        for (int j = 0; j < 4; j++) {
            *(__half2*)&Y[(size_t)(r + i * 16) * M + c + j * 8] =
                __floats2half2_rn(acc[i][j][0], acc[i][j][1]);
            *(__half2*)&Y[(size_t)(r + i * 16 + 8) * M + c + j * 8] =
                __floats2half2_rn(acc[i][j][2], acc[i][j][3]);
        }
    }
}

// ---------------- aggregation: gather fp16 state, fp32 accum, fp16 out -----
__global__ __launch_bounds__(128)
void aggregate_h(const __half* __restrict__ st, const int* __restrict__ rowptr,
                 const int* __restrict__ perm, __half* __restrict__ ph) {
    int i = blockIdx.x * 2 + (threadIdx.x >> 6);
    int c2 = threadIdx.x & 63;
    if (i >= NN) return;
    const __half2* st2 = (const __half2*)st;
    int s0 = rowptr[i], s1 = rowptr[i + 1];
    float ax0 = 0.f, ay0 = 0.f, ax1 = 0.f, ay1 = 0.f;
    int e = s0;
    for (; e + 1 < s1; e += 2) {
        int p0 = perm[e], p1 = perm[e + 1];
        float2 f0 = __half22float2(st2[p0 * 64 + c2]);
        float2 f1 = __half22float2(st2[p1 * 64 + c2]);
        ax0 += f0.x; ay0 += f0.y;
        ax1 += f1.x; ay1 += f1.y;
    }
    if (e < s1) {
        float2 f0 = __half22float2(st2[perm[e] * 64 + c2]);
        ax0 += f0.x; ay0 += f0.y;
    }
    ((__half2*)ph)[i * 64 + c2] = __floats2half2_rn(ax0 + ax1, ay0 + ay1);
}

// ---------------- GRU elementwise (fp16 gates in; fp32 state + fp16 copy) --
__global__ void gru_k(const __half* __restrict__ gi, const __half* __restrict__ gh,
                      const float* __restrict__ b_ih, const float* __restrict__ b_hh,
                      const float* __restrict__ h, float* __restrict__ out,
                      __half* __restrict__ oh, int n4) {
    int idx = blockIdx.x * blockDim.x + threadIdx.x;
    if (idx >= n4) return;
    int i = idx >> 5;
    int c4 = (idx & 31) * 4;
    const __half2* gir = (const __half2*)(gi + (size_t)i * 384 + c4);
    const __half2* ghr = (const __half2*)(gh + (size_t)i * 384 + c4);
    // offsets in half2 units within row: +0 (r), +64 (z), +128 (n)
    float2 ir0 = __half22float2(gir[0]),  ir1 = __half22float2(gir[1]);
    float2 iz0 = __half22float2(gir[64]), iz1 = __half22float2(gir[65]);
    float2 in0 = __half22float2(gir[128]), in1 = __half22float2(gir[129]);
    float2 hr0 = __half22float2(ghr[0]),  hr1 = __half22float2(ghr[1]);
    float2 hz0 = __half22float2(ghr[64]), hz1 = __half22float2(ghr[65]);
    float2 hn0 = __half22float2(ghr[128]), hn1 = __half22float2(ghr[129]);
    float ir[4] = {ir0.x, ir0.y, ir1.x, ir1.y};
    float iz[4] = {iz0.x, iz0.y, iz1.x, iz1.y};
    float in_[4] = {in0.x, in0.y, in1.x, in1.y};
    float hr[4] = {hr0.x, hr0.y, hr1.x, hr1.y};
    float hz[4] = {hz0.x, hz0.y, hz1.x, hz1.y};
    float hn[4] = {hn0.x, hn0.y, hn1.x, hn1.y};

    float4 bir = *(const float4*)(b_ih + c4);
    float4 biz = *(const float4*)(b_ih + 128 + c4);
    float4 bin = *(const float4*)(b_ih + 256 + c4);
    float4 bhr = *(const float4*)(b_hh + c4);
    float4 bhz = *(const float4*)(b_hh + 128 + c4);
    float4 bhn = *(const float4*)(b_hh + 256 + c4);
    float4 hv = *(const float4*)(h + (size_t)i * 128 + c4);

    float o[4];
    #pragma unroll
    for (int q = 0; q < 4; q++) {
        float irq = (ir[q] + (&bir.x)[q]) + (hr[q] + (&bhr.x)[q]);
        float izq = (iz[q] + (&biz.x)[q]) + (hz[q] + (&bhz.x)[q]);
        float inq = in_[q] + (&bin.x)[q];
        float hnq = hn[q] + (&bhn.x)[q];
        float r = 1.f / (1.f + expf(-irq));
        float z = 1.f / (1.f + expf(-izq));
        float nval = tanhf(inq + r * hnq);
        o[q] = (1.f - z) * nval + z * (&hv.x)[q];
    }
    *(float4*)(out + (size_t)i * 128 + c4) = make_float4(o[0], o[1], o[2], o[3]);
    __half2* ohp = (__half2*)(oh + (size_t)i * 128 + c4);
    ohp[0] = __floats2half2_rn(o[0], o[1]);
    ohp[1] = __floats2half2_rn(o[2], o[3]);
}

// ---------------- launcher --------------------------------------------------
extern "C" void kernel_launch(void* const* d_in, const int* in_sizes, int n_in,
                              void* d_out, int out_size) {
    const float* x     = (const float*)d_in[0];
    const int*   ei    = (const int*)d_in[1];
    const float* W_lin = (const float*)d_in[2];
    const float* W_ih  = (const float*)d_in[3];
    const float* W_hh  = (const float*)d_in[4];
    const float* b_ih  = (const float*)d_in[5];
    const float* b_hh  = (const float*)d_in[6];
    float* out = (float*)d_out;

    const int* src = ei;
    const int* dst = ei + EE;

    float *sA_, *sB_, *wc_;
    int *cnt_, *rp_, *perm_, *bsum_;
    __half *gi_, *gh_, *sxh_, *sph_, *whhh_, *whhl_, *wch_, *wcl_;
    cudaGetSymbolAddress((void**)&sA_,   g_sA);
    cudaGetSymbolAddress((void**)&sB_,   g_sB);
    cudaGetSymbolAddress((void**)&gi_,   g_gi);
    cudaGetSymbolAddress((void**)&gh_,   g_gh);
    cudaGetSymbolAddress((void**)&wc_,   g_wcomb);
    cudaGetSymbolAddress((void**)&cnt_,  g_cnt);
    cudaGetSymbolAddress((void**)&rp_,   g_rowptr);
    cudaGetSymbolAddress((void**)&perm_, g_perm);
    cudaGetSymbolAddress((void**)&bsum_, g_bsum);
    cudaGetSymbolAddress((void**)&sxh_,  g_sxh);
    cudaGetSymbolAddress((void**)&sph_,  g_sph);
    cudaGetSymbolAddress((void**)&whhh_, g_whh_h);
    cudaGetSymbolAddress((void**)&whhl_, g_whh_l);
    cudaGetSymbolAddress((void**)&wch_,  g_wc_h);
    cudaGetSymbolAddress((void**)&wcl_,  g_wc_l);

    cudaFuncSetAttribute(gemm_h2, cudaFuncAttributeMaxDynamicSharedMemorySize, G2_SMEM);

    cudaStream_t s2;
    cudaStreamCreateWithFlags(&s2, cudaStreamNonBlocking);
    cudaEvent_t evRoot, evCSR;
    cudaEventCreateWithFlags(&evRoot, cudaEventDisableTiming);
    cudaEventCreateWithFlags(&evCSR,  cudaEventDisableTiming);

    const int NB_SCAN = (NN + 1023) / 1024;
    const int N4 = NN * CC / 4;
    const int NAGG = (NN + 1) / 2;
    const dim3 gg1(RTILES, 6, 1);
    const dim3 gg2(RTILES, 6, 2);

    // ---- prologue; gemm_h2 = my launch #4 (ncu -s 5 -c 1 lands there) ----
    conv_h<<<(N4 + 255) / 256, 256>>>(x, sxh_, N4);                                   // 1
    wsplit<<<(384 * CC + 255) / 256, 256>>>(W_hh, whhh_, whhl_, 384 * CC);            // 2
    zero_pad_h<<<((NPAD - NN) * CC + 255) / 256, 256>>>(sxh_, sph_);                  // 3
    gemm_h2<<<gg1, 256, G2_SMEM>>>(sxh_, whhh_, whhl_, gh_,                           // 4 (profiled)
                                   sxh_, whhh_, whhl_, gh_, 384);
    wcomb_k<<<384, 128>>>(W_ih, W_lin, wc_);
    wsplit<<<(384 * CC + 255) / 256, 256>>>(wc_, wch_, wcl_, 384 * CC);

    // ---- CSR build on side stream (overlaps prologue) ----
    cudaEventRecord(evRoot, 0);
    cudaStreamWaitEvent(s2, evRoot, 0);
    zero_int <<<(NN + 255) / 256, 256, 0, s2>>>(cnt_, NN);
    count_k  <<<(EE + 255) / 256, 256, 0, s2>>>(dst, cnt_);
    scan_block<<<NB_SCAN, 1024, 0, s2>>>(cnt_, rp_, bsum_, NN);
    scan_sums <<<1, 1, 0, s2>>>(bsum_, NB_SCAN);
    add_off   <<<(NN + 255) / 256, 256, 0, s2>>>(rp_, bsum_, NN);
    zero_int  <<<(NN + 255) / 256, 256, 0, s2>>>(cnt_, NN);
    fill_k    <<<(EE + 255) / 256, 256, 0, s2>>>(src, dst, rp_, cnt_, perm_);
    cudaEventRecord(evCSR, s2);
    cudaStreamWaitEvent(0, evCSR, 0);

    // ---- step 0 (gh computed at launch 4); gather fp16 state ----
    aggregate_h<<<NAGG, 128>>>(sxh_, rp_, perm_, sph_);
    gemm_h2<<<gg1, 256, G2_SMEM>>>(sph_, wch_, wcl_, gi_,
                                   sph_, wch_, wcl_, gi_, 384);
    gru_k<<<(N4 + 255) / 256, 256>>>(gi_, gh_, b_ih, b_hh, x, sA_, sxh_, N4);

    // ---- steps 1, 2: merged gi+gh GEMM ----
    aggregate_h<<<NAGG, 128>>>(sxh_, rp_, perm_, sph_);
    gemm_h2<<<gg2, 256, G2_SMEM>>>(sph_, wch_, wcl_, gi_,
                                   sxh_, whhh_, whhl_, gh_, 384);
    gru_k<<<(N4 + 255) / 256, 256>>>(gi_, gh_, b_ih, b_hh, sA_, sB_, sxh_, N4);

    aggregate_h<<<NAGG, 128>>>(sxh_, rp_, perm_, sph_);
    gemm_h2<<<gg2, 256, G2_SMEM>>>(sph_, wch_, wcl_, gi_,
                                   sxh_, whhh_, whhl_, gh_, 384);
    gru_k<<<(N4 + 255) / 256, 256>>>(gi_, gh_, b_ih, b_hh, sB_, out, sxh_, N4);
}

// round 15
// speedup vs baseline: 1.9655x; 1.2299x over previous
#include <cuda_runtime.h>
#include <cuda_bf16.h>
#include <cuda_fp16.h>
#include <cstdint>
#include <math.h>

#define NN 50000
#define CC 128
#define EE 800000
#define NPAD 50048            // 391 * 128
#define RTILES 391

// ---------------- scratch (static device globals; no allocation) ----------
__device__ float g_sA[NN * CC];
__device__ float g_sB[NN * CC];
__device__ __half g_gi[NPAD * 3 * CC];   // input gates, fp16
__device__ __half g_gh[NPAD * 3 * CC];   // hidden gates, fp16
__device__ float g_wcomb[384 * CC];
__device__ int   g_cnt[NN];
__device__ int   g_rowptr[NN + 1];
__device__ int   g_perm[EE];
__device__ int   g_bsum[64];

__device__ __half g_sxh[NPAD * CC];     // state, fp16 (GEMM A + gather src)
__device__ __half g_sph[NPAD * CC];     // prop, fp16 (GEMM A)
__device__ __half g_whh_h[384 * CC];    // W_hh fp16 (single)
__device__ __half g_wc_h[384 * CC];     // W_comb fp16 (single)

// ---------------- PTX helpers ----------------------------------------------
__device__ __forceinline__ uint32_t smem_u32(const void* p) {
    uint32_t a;
    asm("{ .reg .u64 t; cvta.to.shared.u64 t, %1; cvt.u32.u64 %0, t; }" : "=r"(a) : "l"(p));
    return a;
}
__device__ __forceinline__ void ldsm4(uint32_t* r, uint32_t addr) {
    asm volatile("ldmatrix.sync.aligned.m8n8.x4.shared.b16 {%0,%1,%2,%3}, [%4];"
                 : "=r"(r[0]), "=r"(r[1]), "=r"(r[2]), "=r"(r[3]) : "r"(addr));
}
__device__ __forceinline__ void mma_f16(float* d, const uint32_t* a,
                                        uint32_t b0, uint32_t b1) {
    asm volatile(
        "mma.sync.aligned.m16n8k16.row.col.f32.f16.f16.f32 "
        "{%0,%1,%2,%3}, {%4,%5,%6,%7}, {%8,%9}, {%0,%1,%2,%3};"
        : "+f"(d[0]), "+f"(d[1]), "+f"(d[2]), "+f"(d[3])
        : "r"(a[0]), "r"(a[1]), "r"(a[2]), "r"(a[3]), "r"(b0), "r"(b1));
}

// ---------------- small utility kernels -----------------------------------
__global__ void zero_int(int* p, int n) {
    int i = blockIdx.x * blockDim.x + threadIdx.x;
    if (i < n) p[i] = 0;
}

__global__ void zero_pad_h(__half* a, __half* b) {
    int i = blockIdx.x * blockDim.x + threadIdx.x;
    int n = (NPAD - NN) * CC;
    if (i < n) {
        int off = NN * CC + i;
        a[off] = __float2half(0.f);
        b[off] = __float2half(0.f);
    }
}

__global__ void count_k(const int* __restrict__ dst, int* __restrict__ cnt) {
    int e = blockIdx.x * blockDim.x + threadIdx.x;
    if (e < EE) {
        int d = dst[e];
        d = min(max(d, 0), NN - 1);
        atomicAdd(&cnt[d], 1);
    }
}

__global__ void scan_block(const int* __restrict__ cnt, int* __restrict__ excl,
                           int* __restrict__ bsum, int n) {
    __shared__ int sm[1024];
    int t = threadIdx.x;
    int g = blockIdx.x * 1024 + t;
    int v = (g < n) ? cnt[g] : 0;
    sm[t] = v;
    __syncthreads();
    for (int off = 1; off < 1024; off <<= 1) {
        int tv = 0;
        if (t >= off) tv = sm[t - off];
        __syncthreads();
        if (t >= off) sm[t] += tv;
        __syncthreads();
    }
    if (g < n) excl[g] = sm[t] - v;
    if (t == 1023) bsum[blockIdx.x] = sm[1023];
}

__global__ void scan_sums(int* bsum, int nb) {
    int run = 0;
    for (int i = 0; i < nb; i++) { int t = bsum[i]; bsum[i] = run; run += t; }
}

__global__ void add_off(int* __restrict__ rowptr, const int* __restrict__ bsum, int n) {
    int g = blockIdx.x * blockDim.x + threadIdx.x;
    if (g < n) rowptr[g] += bsum[g >> 10];
    if (g == 0) rowptr[n] = EE;
}

__global__ void fill_k(const int* __restrict__ src, const int* __restrict__ dst,
                       const int* __restrict__ rowptr, int* __restrict__ cur,
                       int* __restrict__ perm) {
    int e = blockIdx.x * blockDim.x + threadIdx.x;
    if (e < EE) {
        int d = dst[e];
        d = min(max(d, 0), NN - 1);
        int s = src[e];
        s = min(max(s, 0), NN - 1);
        int pos = rowptr[d] + atomicAdd(&cur[d], 1);
        if (pos >= 0 && pos < EE) perm[pos] = s;
    }
}

// ---------------- W_comb = W_ih @ W_lin (fp32, once) -----------------------
__global__ void wcomb_k(const float* __restrict__ W_ih, const float* __restrict__ W_lin,
                        float* __restrict__ W_comb) {
    int i = blockIdx.x;
    int j = threadIdx.x;
    float s = 0.f;
    #pragma unroll 8
    for (int k = 0; k < 128; k++)
        s += W_ih[i * 128 + k] * W_lin[k * 128 + j];
    W_comb[i * 128 + j] = s;
}

// ---------------- fp32 -> fp16 conversion ----------------------------------
__global__ void conv_h(const float* __restrict__ x, __half* __restrict__ o, int n4) {
    int i = blockIdx.x * blockDim.x + threadIdx.x;
    if (i >= n4) return;
    float4 v = ((const float4*)x)[i];
    __half2* o2 = (__half2*)o;
    o2[i * 2 + 0] = __floats2half2_rn(v.x, v.y);
    o2[i * 2 + 1] = __floats2half2_rn(v.z, v.w);
}

// ---------------- single-fp16 GEMM with staged epilogue --------------------
// Y[NPAD, M] = A[NPAD,128] @ (B[M,128])^T  (fp16 in, fp32 acc, fp16 out)
// block tile 128x64, 256 threads (8 warps 4x2), warp tile 32x32.
// per warp per kstep: 4 ldsm4, 8 MMAs. Epilogue staged through smem for
// coalesced 128B global stores. smem 52224 B -> 2 CTAs/SM.
#define LDSB 136
#define ROWB (LDSB * 2)
#define A_T (128 * LDSB)
#define B_T (64 * LDSB)
#define G1_SMEM ((A_T + B_T) * 2)              // 52224 bytes
#define STG 72                                  // staging row stride (halves)

__global__ __launch_bounds__(256, 2)
void gemm_h1(const __half* __restrict__ A0, const __half* __restrict__ B0,
             __half* __restrict__ Y0,
             const __half* __restrict__ A1, const __half* __restrict__ B1,
             __half* __restrict__ Y1, int M) {
    extern __shared__ __half smh[];
    __half* As = smh;
    __half* Bs = smh + A_T;

    const __half* A = blockIdx.z ? A1 : A0;
    const __half* B = blockIdx.z ? B1 : B0;
    __half* Y = blockIdx.z ? Y1 : Y0;

    int row0 = blockIdx.x * 128;
    int col0 = blockIdx.y * 64;
    int t = threadIdx.x;

    {
        const uint4* gA = (const uint4*)(A + (size_t)row0 * 128);
        #pragma unroll
        for (int i = 0; i < 8; i++) {
            int idx = t + i * 256;
            int r = idx >> 4, c = idx & 15;
            ((uint4*)((char*)As + r * ROWB))[c] = gA[idx];
        }
        const uint4* gB = (const uint4*)(B + (size_t)col0 * 128);
        #pragma unroll
        for (int i = 0; i < 4; i++) {
            int idx = t + i * 256;
            int r = idx >> 4, c = idx & 15;
            ((uint4*)((char*)Bs + r * ROWB))[c] = gB[idx];
        }
    }
    __syncthreads();

    int lane = t & 31;
    int wid = t >> 5;
    int wm = wid & 3;
    int wn = wid >> 2;

    uint32_t laneOff = (uint32_t)((lane & 15) * ROWB + (lane >> 4) * 16);
    uint32_t aP = smem_u32(As) + (uint32_t)(wm * 32) * ROWB + laneOff;
    uint32_t bP = smem_u32(Bs) + (uint32_t)(wn * 32) * ROWB + laneOff;

    float acc[2][4][4];
    #pragma unroll
    for (int i = 0; i < 2; i++)
        #pragma unroll
        for (int j = 0; j < 4; j++)
            #pragma unroll
            for (int q = 0; q < 4; q++) acc[i][j][q] = 0.f;

    #pragma unroll
    for (int ks = 0; ks < 8; ks++) {
        uint32_t kb = ks * 32;
        uint32_t a0[4], a1[4], p0[4], p1[4];
        ldsm4(a0, aP + kb);
        ldsm4(a1, aP + 16 * ROWB + kb);
        ldsm4(p0, bP + kb);
        ldsm4(p1, bP + 16 * ROWB + kb);
        mma_f16(acc[0][0], a0, p0[0], p0[2]);
        mma_f16(acc[0][1], a0, p0[1], p0[3]);
        mma_f16(acc[0][2], a0, p1[0], p1[2]);
        mma_f16(acc[0][3], a0, p1[1], p1[3]);
        mma_f16(acc[1][0], a1, p0[0], p0[2]);
        mma_f16(acc[1][1], a1, p0[1], p0[3]);
        mma_f16(acc[1][2], a1, p1[0], p1[2]);
        mma_f16(acc[1][3], a1, p1[1], p1[3]);
    }

    // ---- staged epilogue: acc -> smem (conflict-free) -> coalesced global --
    __syncthreads();                       // done reading As/Bs
    __half* stg = smh;                     // 128 x STG halves = 18432 B
    {
        int rbase = wm * 32 + (lane >> 2);
        int cbase = wn * 32 + (lane & 3) * 2;
        #pragma unroll
        for (int i = 0; i < 2; i++) {
            #pragma unroll
            for (int j = 0; j < 4; j++) {
                *(__half2*)&stg[(rbase + i * 16) * STG + cbase + j * 8] =
                    __floats2half2_rn(acc[i][j][0], acc[i][j][1]);
                *(__half2*)&stg[(rbase + i * 16 + 8) * STG + cbase + j * 8] =
                    __floats2half2_rn(acc[i][j][2], acc[i][j][3]);
            }
        }
    }
    __syncthreads();
    {
        #pragma unroll
        for (int it = 0; it < 4; it++) {
            int idx = t + it * 256;        // 0..1023
            int r = idx >> 3;
            int c8 = idx & 7;
            uint4 v = *(const uint4*)&stg[r * STG + c8 * 8];
            *(uint4*)&Y[(size_t)(row0 + r) * M + col0 + c8 * 8] = v;
        }
    }
}

// ---------------- aggregation: gather fp16 state, fp32 accum, fp16 out -----
__global__ __launch_bounds__(128)
void aggregate_h(const __half* __restrict__ st, const int* __restrict__ rowptr,
                 const int* __restrict__ perm, __half* __restrict__ ph) {
    int i = blockIdx.x * 2 + (threadIdx.x >> 6);
    int c2 = threadIdx.x & 63;
    if (i >= NN) return;
    const __half2* st2 = (const __half2*)st;
    int s0 = rowptr[i], s1 = rowptr[i + 1];
    float ax0 = 0.f, ay0 = 0.f, ax1 = 0.f, ay1 = 0.f;
    int e = s0;
    for (; e + 1 < s1; e += 2) {
        int p0 = perm[e], p1 = perm[e + 1];
        float2 f0 = __half22float2(st2[p0 * 64 + c2]);
        float2 f1 = __half22float2(st2[p1 * 64 + c2]);
        ax0 += f0.x; ay0 += f0.y;
        ax1 += f1.x; ay1 += f1.y;
    }
    if (e < s1) {
        float2 f0 = __half22float2(st2[perm[e] * 64 + c2]);
        ax0 += f0.x; ay0 += f0.y;
    }
    ((__half2*)ph)[i * 64 + c2] = __floats2half2_rn(ax0 + ax1, ay0 + ay1);
}

// ---------------- GRU elementwise (fp16 gates in; fp32 state + fp16 copy) --
__global__ void gru_k(const __half* __restrict__ gi, const __half* __restrict__ gh,
                      const float* __restrict__ b_ih, const float* __restrict__ b_hh,
                      const float* __restrict__ h, float* __restrict__ out,
                      __half* __restrict__ oh, int n4) {
    int idx = blockIdx.x * blockDim.x + threadIdx.x;
    if (idx >= n4) return;
    int i = idx >> 5;
    int c4 = (idx & 31) * 4;
    const __half2* gir = (const __half2*)(gi + (size_t)i * 384 + c4);
    const __half2* ghr = (const __half2*)(gh + (size_t)i * 384 + c4);
    float2 ir0 = __half22float2(gir[0]),  ir1 = __half22float2(gir[1]);
    float2 iz0 = __half22float2(gir[64]), iz1 = __half22float2(gir[65]);
    float2 in0 = __half22float2(gir[128]), in1 = __half22float2(gir[129]);
    float2 hr0 = __half22float2(ghr[0]),  hr1 = __half22float2(ghr[1]);
    float2 hz0 = __half22float2(ghr[64]), hz1 = __half22float2(ghr[65]);
    float2 hn0 = __half22float2(ghr[128]), hn1 = __half22float2(ghr[129]);
    float ir[4] = {ir0.x, ir0.y, ir1.x, ir1.y};
    float iz[4] = {iz0.x, iz0.y, iz1.x, iz1.y};
    float in_[4] = {in0.x, in0.y, in1.x, in1.y};
    float hr[4] = {hr0.x, hr0.y, hr1.x, hr1.y};
    float hz[4] = {hz0.x, hz0.y, hz1.x, hz1.y};
    float hn[4] = {hn0.x, hn0.y, hn1.x, hn1.y};

    float4 bir = *(const float4*)(b_ih + c4);
    float4 biz = *(const float4*)(b_ih + 128 + c4);
    float4 bin = *(const float4*)(b_ih + 256 + c4);
    float4 bhr = *(const float4*)(b_hh + c4);
    float4 bhz = *(const float4*)(b_hh + 128 + c4);
    float4 bhn = *(const float4*)(b_hh + 256 + c4);
    float4 hv = *(const float4*)(h + (size_t)i * 128 + c4);

    float o[4];
    #pragma unroll
    for (int q = 0; q < 4; q++) {
        float irq = (ir[q] + (&bir.x)[q]) + (hr[q] + (&bhr.x)[q]);
        float izq = (iz[q] + (&biz.x)[q]) + (hz[q] + (&bhz.x)[q]);
        float inq = in_[q] + (&bin.x)[q];
        float hnq = hn[q] + (&bhn.x)[q];
        float r = 1.f / (1.f + expf(-irq));
        float z = 1.f / (1.f + expf(-izq));
        float nval = tanhf(inq + r * hnq);
        o[q] = (1.f - z) * nval + z * (&hv.x)[q];
    }
    *(float4*)(out + (size_t)i * 128 + c4) = make_float4(o[0], o[1], o[2], o[3]);
    __half2* ohp = (__half2*)(oh + (size_t)i * 128 + c4);
    ohp[0] = __floats2half2_rn(o[0], o[1]);
    ohp[1] = __floats2half2_rn(o[2], o[3]);
}

// ---------------- launcher --------------------------------------------------
extern "C" void kernel_launch(void* const* d_in, const int* in_sizes, int n_in,
                              void* d_out, int out_size) {
    const float* x     = (const float*)d_in[0];
    const int*   ei    = (const int*)d_in[1];
    const float* W_lin = (const float*)d_in[2];
    const float* W_ih  = (const float*)d_in[3];
    const float* W_hh  = (const float*)d_in[4];
    const float* b_ih  = (const float*)d_in[5];
    const float* b_hh  = (const float*)d_in[6];
    float* out = (float*)d_out;

    const int* src = ei;
    const int* dst = ei + EE;

    float *sA_, *sB_, *wc_;
    int *cnt_, *rp_, *perm_, *bsum_;
    __half *gi_, *gh_, *sxh_, *sph_, *whhh_, *wch_;
    cudaGetSymbolAddress((void**)&sA_,   g_sA);
    cudaGetSymbolAddress((void**)&sB_,   g_sB);
    cudaGetSymbolAddress((void**)&gi_,   g_gi);
    cudaGetSymbolAddress((void**)&gh_,   g_gh);
    cudaGetSymbolAddress((void**)&wc_,   g_wcomb);
    cudaGetSymbolAddress((void**)&cnt_,  g_cnt);
    cudaGetSymbolAddress((void**)&rp_,   g_rowptr);
    cudaGetSymbolAddress((void**)&perm_, g_perm);
    cudaGetSymbolAddress((void**)&bsum_, g_bsum);
    cudaGetSymbolAddress((void**)&sxh_,  g_sxh);
    cudaGetSymbolAddress((void**)&sph_,  g_sph);
    cudaGetSymbolAddress((void**)&whhh_, g_whh_h);
    cudaGetSymbolAddress((void**)&wch_,  g_wc_h);

    cudaFuncSetAttribute(gemm_h1, cudaFuncAttributeMaxDynamicSharedMemorySize, G1_SMEM);

    cudaStream_t s2;
    cudaStreamCreateWithFlags(&s2, cudaStreamNonBlocking);
    cudaEvent_t evRoot, evCSR;
    cudaEventCreateWithFlags(&evRoot, cudaEventDisableTiming);
    cudaEventCreateWithFlags(&evCSR,  cudaEventDisableTiming);

    const int NB_SCAN = (NN + 1023) / 1024;
    const int N4 = NN * CC / 4;
    const int NAGG = (NN + 1) / 2;
    const dim3 gg1(RTILES, 6, 1);
    const dim3 gg2(RTILES, 6, 2);

    // ---- prologue; gemm_h1 = my launch #4 (ncu -s 5 -c 1 lands there) ----
    conv_h<<<(N4 + 255) / 256, 256>>>(x, sxh_, N4);                                   // 1
    conv_h<<<(384 * CC / 4 + 255) / 256, 256>>>(W_hh, whhh_, 384 * CC / 4);           // 2
    zero_pad_h<<<((NPAD - NN) * CC + 255) / 256, 256>>>(sxh_, sph_);                  // 3
    gemm_h1<<<gg1, 256, G1_SMEM>>>(sxh_, whhh_, gh_,                                  // 4 (profiled)
                                   sxh_, whhh_, gh_, 384);
    wcomb_k<<<384, 128>>>(W_ih, W_lin, wc_);
    conv_h<<<(384 * CC / 4 + 255) / 256, 256>>>(wc_, wch_, 384 * CC / 4);

    // ---- CSR build on side stream (overlaps prologue) ----
    cudaEventRecord(evRoot, 0);
    cudaStreamWaitEvent(s2, evRoot, 0);
    zero_int <<<(NN + 255) / 256, 256, 0, s2>>>(cnt_, NN);
    count_k  <<<(EE + 255) / 256, 256, 0, s2>>>(dst, cnt_);
    scan_block<<<NB_SCAN, 1024, 0, s2>>>(cnt_, rp_, bsum_, NN);
    scan_sums <<<1, 1, 0, s2>>>(bsum_, NB_SCAN);
    add_off   <<<(NN + 255) / 256, 256, 0, s2>>>(rp_, bsum_, NN);
    zero_int  <<<(NN + 255) / 256, 256, 0, s2>>>(cnt_, NN);
    fill_k    <<<(EE + 255) / 256, 256, 0, s2>>>(src, dst, rp_, cnt_, perm_);
    cudaEventRecord(evCSR, s2);
    cudaStreamWaitEvent(0, evCSR, 0);

    // ---- step 0 (gh computed at launch 4) ----
    aggregate_h<<<NAGG, 128>>>(sxh_, rp_, perm_, sph_);
    gemm_h1<<<gg1, 256, G1_SMEM>>>(sph_, wch_, gi_,
                                   sph_, wch_, gi_, 384);
    gru_k<<<(N4 + 255) / 256, 256>>>(gi_, gh_, b_ih, b_hh, x, sA_, sxh_, N4);

    // ---- steps 1, 2: merged gi+gh GEMM ----
    aggregate_h<<<NAGG, 128>>>(sxh_, rp_, perm_, sph_);
    gemm_h1<<<gg2, 256, G1_SMEM>>>(sph_, wch_, gi_,
                                   sxh_, whhh_, gh_, 384);
    gru_k<<<(N4 + 255) / 256, 256>>>(gi_, gh_, b_ih, b_hh, sA_, sB_, sxh_, N4);

    aggregate_h<<<NAGG, 128>>>(sxh_, rp_, perm_, sph_);
    gemm_h1<<<gg2, 256, G1_SMEM>>>(sph_, wch_, gi_,
                                   sxh_, whhh_, gh_, 384);
    gru_k<<<(N4 + 255) / 256, 256>>>(gi_, gh_, b_ih, b_hh, sB_, out, sxh_, N4);
}

// round 16
// speedup vs baseline: 1.9976x; 1.0163x over previous
#include <cuda_runtime.h>
#include <cuda_bf16.h>
#include <cuda_fp16.h>
#include <cstdint>
#include <math.h>

#define NN 50000
#define CC 128
#define EE 800000
#define NPAD 50048            // 391 * 128
#define RTILES 391

// ---------------- scratch (static device globals; no allocation) ----------
__device__ float g_sA[NN * CC];
__device__ float g_sB[NN * CC];
__device__ __half g_gi[NPAD * 3 * CC];   // input gates, fp16
__device__ __half g_gh[NPAD * 3 * CC];   // hidden gates, fp16
__device__ float g_wcomb[384 * CC];
__device__ int   g_cnt[NN];
__device__ int   g_rowptr[NN + 1];
__device__ int   g_perm[EE];
__device__ int   g_bsum[64];

__device__ __half g_sxh[NPAD * CC];     // state, fp16 (GEMM A + gather src)
__device__ __half g_sph[NPAD * CC];     // prop, fp16 (GEMM A)
__device__ __half g_whh_h[384 * CC];    // W_hh fp16 (single)
__device__ __half g_wc_h[384 * CC];     // W_comb fp16 (single)

// ---------------- PTX helpers ----------------------------------------------
__device__ __forceinline__ uint32_t smem_u32(const void* p) {
    uint32_t a;
    asm("{ .reg .u64 t; cvta.to.shared.u64 t, %1; cvt.u32.u64 %0, t; }" : "=r"(a) : "l"(p));
    return a;
}
__device__ __forceinline__ void ldsm4(uint32_t* r, uint32_t addr) {
    asm volatile("ldmatrix.sync.aligned.m8n8.x4.shared.b16 {%0,%1,%2,%3}, [%4];"
                 : "=r"(r[0]), "=r"(r[1]), "=r"(r[2]), "=r"(r[3]) : "r"(addr));
}
__device__ __forceinline__ void mma_f16(float* d, const uint32_t* a,
                                        uint32_t b0, uint32_t b1) {
    asm volatile(
        "mma.sync.aligned.m16n8k16.row.col.f32.f16.f16.f32 "
        "{%0,%1,%2,%3}, {%4,%5,%6,%7}, {%8,%9}, {%0,%1,%2,%3};"
        : "+f"(d[0]), "+f"(d[1]), "+f"(d[2]), "+f"(d[3])
        : "r"(a[0]), "r"(a[1]), "r"(a[2]), "r"(a[3]), "r"(b0), "r"(b1));
}

// ---------------- small utility kernels -----------------------------------
__global__ void zero_int(int* p, int n) {
    int i = blockIdx.x * blockDim.x + threadIdx.x;
    if (i < n) p[i] = 0;
}

__global__ void zero_pad_h(__half* a, __half* b) {
    int i = blockIdx.x * blockDim.x + threadIdx.x;
    int n = (NPAD - NN) * CC;
    if (i < n) {
        int off = NN * CC + i;
        a[off] = __float2half(0.f);
        b[off] = __float2half(0.f);
    }
}

__global__ void count_k(const int* __restrict__ dst, int* __restrict__ cnt) {
    int e = blockIdx.x * blockDim.x + threadIdx.x;
    if (e < EE) {
        int d = dst[e];
        d = min(max(d, 0), NN - 1);
        atomicAdd(&cnt[d], 1);
    }
}

__global__ void scan_block(const int* __restrict__ cnt, int* __restrict__ excl,
                           int* __restrict__ bsum, int n) {
    __shared__ int sm[1024];
    int t = threadIdx.x;
    int g = blockIdx.x * 1024 + t;
    int v = (g < n) ? cnt[g] : 0;
    sm[t] = v;
    __syncthreads();
    for (int off = 1; off < 1024; off <<= 1) {
        int tv = 0;
        if (t >= off) tv = sm[t - off];
        __syncthreads();
        if (t >= off) sm[t] += tv;
        __syncthreads();
    }
    if (g < n) excl[g] = sm[t] - v;
    if (t == 1023) bsum[blockIdx.x] = sm[1023];
}

__global__ void scan_sums(int* bsum, int nb) {
    int run = 0;
    for (int i = 0; i < nb; i++) { int t = bsum[i]; bsum[i] = run; run += t; }
}

__global__ void add_off(int* __restrict__ rowptr, const int* __restrict__ bsum, int n) {
    int g = blockIdx.x * blockDim.x + threadIdx.x;
    if (g < n) rowptr[g] += bsum[g >> 10];
    if (g == 0) rowptr[n] = EE;
}

__global__ void fill_k(const int* __restrict__ src, const int* __restrict__ dst,
                       const int* __restrict__ rowptr, int* __restrict__ cur,
                       int* __restrict__ perm) {
    int e = blockIdx.x * blockDim.x + threadIdx.x;
    if (e < EE) {
        int d = dst[e];
        d = min(max(d, 0), NN - 1);
        int s = src[e];
        s = min(max(s, 0), NN - 1);
        int pos = rowptr[d] + atomicAdd(&cur[d], 1);
        if (pos >= 0 && pos < EE) perm[pos] = s;
    }
}

// ---------------- W_comb = W_ih @ W_lin (fp32, once) -----------------------
__global__ void wcomb_k(const float* __restrict__ W_ih, const float* __restrict__ W_lin,
                        float* __restrict__ W_comb) {
    int i = blockIdx.x;
    int j = threadIdx.x;
    float s = 0.f;
    #pragma unroll 8
    for (int k = 0; k < 128; k++)
        s += W_ih[i * 128 + k] * W_lin[k * 128 + j];
    W_comb[i * 128 + j] = s;
}

// ---------------- fp32 -> fp16 conversion ----------------------------------
__global__ void conv_h(const float* __restrict__ x, __half* __restrict__ o, int n4) {
    int i = blockIdx.x * blockDim.x + threadIdx.x;
    if (i >= n4) return;
    float4 v = ((const float4*)x)[i];
    __half2* o2 = (__half2*)o;
    o2[i * 2 + 0] = __floats2half2_rn(v.x, v.y);
    o2[i * 2 + 1] = __floats2half2_rn(v.z, v.w);
}

// ---------------- single-fp16 GEMM with staged epilogue --------------------
#define LDSB 136
#define ROWB (LDSB * 2)
#define A_T (128 * LDSB)
#define B_T (64 * LDSB)
#define G1_SMEM ((A_T + B_T) * 2)              // 52224 bytes
#define STG 72                                  // staging row stride (halves)

__global__ __launch_bounds__(256, 2)
void gemm_h1(const __half* __restrict__ A0, const __half* __restrict__ B0,
             __half* __restrict__ Y0,
             const __half* __restrict__ A1, const __half* __restrict__ B1,
             __half* __restrict__ Y1, int M) {
    extern __shared__ __half smh[];
    __half* As = smh;
    __half* Bs = smh + A_T;

    const __half* A = blockIdx.z ? A1 : A0;
    const __half* B = blockIdx.z ? B1 : B0;
    __half* Y = blockIdx.z ? Y1 : Y0;

    int row0 = blockIdx.x * 128;
    int col0 = blockIdx.y * 64;
    int t = threadIdx.x;

    {
        const uint4* gA = (const uint4*)(A + (size_t)row0 * 128);
        #pragma unroll
        for (int i = 0; i < 8; i++) {
            int idx = t + i * 256;
            int r = idx >> 4, c = idx & 15;
            ((uint4*)((char*)As + r * ROWB))[c] = gA[idx];
        }
        const uint4* gB = (const uint4*)(B + (size_t)col0 * 128);
        #pragma unroll
        for (int i = 0; i < 4; i++) {
            int idx = t + i * 256;
            int r = idx >> 4, c = idx & 15;
            ((uint4*)((char*)Bs + r * ROWB))[c] = gB[idx];
        }
    }
    __syncthreads();

    int lane = t & 31;
    int wid = t >> 5;
    int wm = wid & 3;
    int wn = wid >> 2;

    uint32_t laneOff = (uint32_t)((lane & 15) * ROWB + (lane >> 4) * 16);
    uint32_t aP = smem_u32(As) + (uint32_t)(wm * 32) * ROWB + laneOff;
    uint32_t bP = smem_u32(Bs) + (uint32_t)(wn * 32) * ROWB + laneOff;

    float acc[2][4][4];
    #pragma unroll
    for (int i = 0; i < 2; i++)
        #pragma unroll
        for (int j = 0; j < 4; j++)
            #pragma unroll
            for (int q = 0; q < 4; q++) acc[i][j][q] = 0.f;

    #pragma unroll
    for (int ks = 0; ks < 8; ks++) {
        uint32_t kb = ks * 32;
        uint32_t a0[4], a1[4], p0[4], p1[4];
        ldsm4(a0, aP + kb);
        ldsm4(a1, aP + 16 * ROWB + kb);
        ldsm4(p0, bP + kb);
        ldsm4(p1, bP + 16 * ROWB + kb);
        mma_f16(acc[0][0], a0, p0[0], p0[2]);
        mma_f16(acc[0][1], a0, p0[1], p0[3]);
        mma_f16(acc[0][2], a0, p1[0], p1[2]);
        mma_f16(acc[0][3], a0, p1[1], p1[3]);
        mma_f16(acc[1][0], a1, p0[0], p0[2]);
        mma_f16(acc[1][1], a1, p0[1], p0[3]);
        mma_f16(acc[1][2], a1, p1[0], p1[2]);
        mma_f16(acc[1][3], a1, p1[1], p1[3]);
    }

    // ---- staged epilogue: acc -> smem (conflict-free) -> coalesced global --
    __syncthreads();
    __half* stg = smh;
    {
        int rbase = wm * 32 + (lane >> 2);
        int cbase = wn * 32 + (lane & 3) * 2;
        #pragma unroll
        for (int i = 0; i < 2; i++) {
            #pragma unroll
            for (int j = 0; j < 4; j++) {
                *(__half2*)&stg[(rbase + i * 16) * STG + cbase + j * 8] =
                    __floats2half2_rn(acc[i][j][0], acc[i][j][1]);
                *(__half2*)&stg[(rbase + i * 16 + 8) * STG + cbase + j * 8] =
                    __floats2half2_rn(acc[i][j][2], acc[i][j][3]);
            }
        }
    }
    __syncthreads();
    {
        #pragma unroll
        for (int it = 0; it < 4; it++) {
            int idx = t + it * 256;
            int r = idx >> 3;
            int c8 = idx & 7;
            uint4 v = *(const uint4*)&stg[r * STG + c8 * 8];
            *(uint4*)&Y[(size_t)(row0 + r) * M + col0 + c8 * 8] = v;
        }
    }
}

// ---------------- aggregation: gather fp16 state, fp32 accum, fp16 out -----
__global__ __launch_bounds__(128)
void aggregate_h(const __half* __restrict__ st, const int* __restrict__ rowptr,
                 const int* __restrict__ perm, __half* __restrict__ ph) {
    int i = blockIdx.x * 2 + (threadIdx.x >> 6);
    int c2 = threadIdx.x & 63;
    if (i >= NN) return;
    const __half2* st2 = (const __half2*)st;
    int s0 = rowptr[i], s1 = rowptr[i + 1];
    float ax0 = 0.f, ay0 = 0.f, ax1 = 0.f, ay1 = 0.f;
    int e = s0;
    for (; e + 1 < s1; e += 2) {
        int p0 = perm[e], p1 = perm[e + 1];
        float2 f0 = __half22float2(st2[p0 * 64 + c2]);
        float2 f1 = __half22float2(st2[p1 * 64 + c2]);
        ax0 += f0.x; ay0 += f0.y;
        ax1 += f1.x; ay1 += f1.y;
    }
    if (e < s1) {
        float2 f0 = __half22float2(st2[perm[e] * 64 + c2]);
        ax0 += f0.x; ay0 += f0.y;
    }
    ((__half2*)ph)[i * 64 + c2] = __floats2half2_rn(ax0 + ax1, ay0 + ay1);
}

// ---------------- GRU elementwise (fp16 gates in; fp32 state + fp16 copy) --
__global__ void gru_k(const __half* __restrict__ gi, const __half* __restrict__ gh,
                      const float* __restrict__ b_ih, const float* __restrict__ b_hh,
                      const float* __restrict__ h, float* __restrict__ out,
                      __half* __restrict__ oh, int n4) {
    int idx = blockIdx.x * blockDim.x + threadIdx.x;
    if (idx >= n4) return;
    int i = idx >> 5;
    int c4 = (idx & 31) * 4;
    const __half2* gir = (const __half2*)(gi + (size_t)i * 384 + c4);
    const __half2* ghr = (const __half2*)(gh + (size_t)i * 384 + c4);
    float2 ir0 = __half22float2(gir[0]),  ir1 = __half22float2(gir[1]);
    float2 iz0 = __half22float2(gir[64]), iz1 = __half22float2(gir[65]);
    float2 in0 = __half22float2(gir[128]), in1 = __half22float2(gir[129]);
    float2 hr0 = __half22float2(ghr[0]),  hr1 = __half22float2(ghr[1]);
    float2 hz0 = __half22float2(ghr[64]), hz1 = __half22float2(ghr[65]);
    float2 hn0 = __half22float2(ghr[128]), hn1 = __half22float2(ghr[129]);
    float ir[4] = {ir0.x, ir0.y, ir1.x, ir1.y};
    float iz[4] = {iz0.x, iz0.y, iz1.x, iz1.y};
    float in_[4] = {in0.x, in0.y, in1.x, in1.y};
    float hr[4] = {hr0.x, hr0.y, hr1.x, hr1.y};
    float hz[4] = {hz0.x, hz0.y, hz1.x, hz1.y};
    float hn[4] = {hn0.x, hn0.y, hn1.x, hn1.y};

    float4 bir = *(const float4*)(b_ih + c4);
    float4 biz = *(const float4*)(b_ih + 128 + c4);
    float4 bin = *(const float4*)(b_ih + 256 + c4);
    float4 bhr = *(const float4*)(b_hh + c4);
    float4 bhz = *(const float4*)(b_hh + 128 + c4);
    float4 bhn = *(const float4*)(b_hh + 256 + c4);
    float4 hv = *(const float4*)(h + (size_t)i * 128 + c4);

    float o[4];
    #pragma unroll
    for (int q = 0; q < 4; q++) {
        float irq = (ir[q] + (&bir.x)[q]) + (hr[q] + (&bhr.x)[q]);
        float izq = (iz[q] + (&biz.x)[q]) + (hz[q] + (&bhz.x)[q]);
        float inq = in_[q] + (&bin.x)[q];
        float hnq = hn[q] + (&bhn.x)[q];
        float r = 1.f / (1.f + expf(-irq));
        float z = 1.f / (1.f + expf(-izq));
        float nval = tanhf(inq + r * hnq);
        o[q] = (1.f - z) * nval + z * (&hv.x)[q];
    }
    *(float4*)(out + (size_t)i * 128 + c4) = make_float4(o[0], o[1], o[2], o[3]);
    __half2* ohp = (__half2*)(oh + (size_t)i * 128 + c4);
    ohp[0] = __floats2half2_rn(o[0], o[1]);
    ohp[1] = __floats2half2_rn(o[2], o[3]);
}

// ---------------- launcher --------------------------------------------------
extern "C" void kernel_launch(void* const* d_in, const int* in_sizes, int n_in,
                              void* d_out, int out_size) {
    const float* x     = (const float*)d_in[0];
    const int*   ei    = (const int*)d_in[1];
    const float* W_lin = (const float*)d_in[2];
    const float* W_ih  = (const float*)d_in[3];
    const float* W_hh  = (const float*)d_in[4];
    const float* b_ih  = (const float*)d_in[5];
    const float* b_hh  = (const float*)d_in[6];
    float* out = (float*)d_out;

    const int* src = ei;
    const int* dst = ei + EE;

    float *sA_, *sB_, *wc_;
    int *cnt_, *rp_, *perm_, *bsum_;
    __half *gi_, *gh_, *sxh_, *sph_, *whhh_, *wch_;
    cudaGetSymbolAddress((void**)&sA_,   g_sA);
    cudaGetSymbolAddress((void**)&sB_,   g_sB);
    cudaGetSymbolAddress((void**)&gi_,   g_gi);
    cudaGetSymbolAddress((void**)&gh_,   g_gh);
    cudaGetSymbolAddress((void**)&wc_,   g_wcomb);
    cudaGetSymbolAddress((void**)&cnt_,  g_cnt);
    cudaGetSymbolAddress((void**)&rp_,   g_rowptr);
    cudaGetSymbolAddress((void**)&perm_, g_perm);
    cudaGetSymbolAddress((void**)&bsum_, g_bsum);
    cudaGetSymbolAddress((void**)&sxh_,  g_sxh);
    cudaGetSymbolAddress((void**)&sph_,  g_sph);
    cudaGetSymbolAddress((void**)&whhh_, g_whh_h);
    cudaGetSymbolAddress((void**)&wch_,  g_wc_h);

    cudaFuncSetAttribute(gemm_h1, cudaFuncAttributeMaxDynamicSharedMemorySize, G1_SMEM);

    cudaStream_t s2;
    cudaStreamCreateWithFlags(&s2, cudaStreamNonBlocking);
    cudaEvent_t evRoot, evCSR, evGru1, evGh1, evGru2, evGh2;
    cudaEventCreateWithFlags(&evRoot, cudaEventDisableTiming);
    cudaEventCreateWithFlags(&evCSR,  cudaEventDisableTiming);
    cudaEventCreateWithFlags(&evGru1, cudaEventDisableTiming);
    cudaEventCreateWithFlags(&evGh1,  cudaEventDisableTiming);
    cudaEventCreateWithFlags(&evGru2, cudaEventDisableTiming);
    cudaEventCreateWithFlags(&evGh2,  cudaEventDisableTiming);

    const int NB_SCAN = (NN + 1023) / 1024;
    const int N4 = NN * CC / 4;
    const int NAGG = (NN + 1) / 2;
    const dim3 gg1(RTILES, 6, 1);

    // ---- prologue; gemm_h1 = my launch #4 (ncu -s 5 -c 1 lands there) ----
    conv_h<<<(N4 + 255) / 256, 256>>>(x, sxh_, N4);                                   // 1
    conv_h<<<(384 * CC / 4 + 255) / 256, 256>>>(W_hh, whhh_, 384 * CC / 4);           // 2
    zero_pad_h<<<((NPAD - NN) * CC + 255) / 256, 256>>>(sxh_, sph_);                  // 3
    gemm_h1<<<gg1, 256, G1_SMEM>>>(sxh_, whhh_, gh_,                                  // 4 (profiled)
                                   sxh_, whhh_, gh_, 384);
    wcomb_k<<<384, 128>>>(W_ih, W_lin, wc_);
    conv_h<<<(384 * CC / 4 + 255) / 256, 256>>>(wc_, wch_, 384 * CC / 4);

    // ---- CSR build on side stream (overlaps prologue) ----
    cudaEventRecord(evRoot, 0);
    cudaStreamWaitEvent(s2, evRoot, 0);
    zero_int <<<(NN + 255) / 256, 256, 0, s2>>>(cnt_, NN);
    count_k  <<<(EE + 255) / 256, 256, 0, s2>>>(dst, cnt_);
    scan_block<<<NB_SCAN, 1024, 0, s2>>>(cnt_, rp_, bsum_, NN);
    scan_sums <<<1, 1, 0, s2>>>(bsum_, NB_SCAN);
    add_off   <<<(NN + 255) / 256, 256, 0, s2>>>(rp_, bsum_, NN);
    zero_int  <<<(NN + 255) / 256, 256, 0, s2>>>(cnt_, NN);
    fill_k    <<<(EE + 255) / 256, 256, 0, s2>>>(src, dst, rp_, cnt_, perm_);
    cudaEventRecord(evCSR, s2);
    cudaStreamWaitEvent(0, evCSR, 0);

    // ---- step 0 (gh computed at launch 4) ----
    aggregate_h<<<NAGG, 128>>>(sxh_, rp_, perm_, sph_);
    gemm_h1<<<gg1, 256, G1_SMEM>>>(sph_, wch_, gi_,
                                   sph_, wch_, gi_, 384);
    gru_k<<<(N4 + 255) / 256, 256>>>(gi_, gh_, b_ih, b_hh, x, sA_, sxh_, N4);

    // ---- step 1: gh GEMM (s2) overlaps aggregate (main); regs now allow
    //      co-residency (gemm 36K regs/SM, aggregate blocks fill the rest) ----
    cudaEventRecord(evGru1, 0);
    cudaStreamWaitEvent(s2, evGru1, 0);
    gemm_h1<<<gg1, 256, G1_SMEM, s2>>>(sxh_, whhh_, gh_,
                                       sxh_, whhh_, gh_, 384);
    cudaEventRecord(evGh1, s2);
    aggregate_h<<<NAGG, 128>>>(sxh_, rp_, perm_, sph_);
    gemm_h1<<<gg1, 256, G1_SMEM>>>(sph_, wch_, gi_,
                                   sph_, wch_, gi_, 384);
    cudaStreamWaitEvent(0, evGh1, 0);
    gru_k<<<(N4 + 255) / 256, 256>>>(gi_, gh_, b_ih, b_hh, sA_, sB_, sxh_, N4);

    // ---- step 2 ----
    cudaEventRecord(evGru2, 0);
    cudaStreamWaitEvent(s2, evGru2, 0);
    gemm_h1<<<gg1, 256, G1_SMEM, s2>>>(sxh_, whhh_, gh_,
                                       sxh_, whhh_, gh_, 384);
    cudaEventRecord(evGh2, s2);
    aggregate_h<<<NAGG, 128>>>(sxh_, rp_, perm_, sph_);
    gemm_h1<<<gg1, 256, G1_SMEM>>>(sph_, wch_, gi_,
                                   sph_, wch_, gi_, 384);
    cudaStreamWaitEvent(0, evGh2, 0);
    gru_k<<<(N4 + 255) / 256, 256>>>(gi_, gh_, b_ih, b_hh, sB_, out, sxh_, N4);
}

// round 17
// speedup vs baseline: 2.0946x; 1.0485x over previous
#include <cuda_runtime.h>
#include <cuda_bf16.h>
#include <cuda_fp16.h>
#include <cstdint>
#include <math.h>

#define NN 50000
#define CC 128
#define EE 800000
#define NPAD 50048            // 391 * 128
#define RTILES 391

// ---------------- scratch (static device globals; no allocation) ----------
__device__ float g_sA[NN * CC];
__device__ float g_sB[NN * CC];
__device__ __half g_gi[NPAD * 3 * CC];   // input gates, fp16
__device__ __half g_gh[NPAD * 3 * CC];   // hidden gates, fp16
__device__ float g_wcomb[384 * CC];
__device__ int   g_cnt[NN];
__device__ int   g_rowptr[NN + 1];
__device__ int   g_perm[EE];
__device__ int   g_bsum[64];

__device__ __half g_sxh[NPAD * CC];     // state, fp16 (GEMM A + gather src)
__device__ __half g_sph[NPAD * CC];     // prop, fp16 (GEMM A)
__device__ __half g_whh_h[384 * CC];    // W_hh fp16 (single)
__device__ __half g_wc_h[384 * CC];     // W_comb fp16 (single)

// ---------------- PTX helpers ----------------------------------------------
__device__ __forceinline__ uint32_t smem_u32(const void* p) {
    uint32_t a;
    asm("{ .reg .u64 t; cvta.to.shared.u64 t, %1; cvt.u32.u64 %0, t; }" : "=r"(a) : "l"(p));
    return a;
}
__device__ __forceinline__ void ldsm4(uint32_t* r, uint32_t addr) {
    asm volatile("ldmatrix.sync.aligned.m8n8.x4.shared.b16 {%0,%1,%2,%3}, [%4];"
                 : "=r"(r[0]), "=r"(r[1]), "=r"(r[2]), "=r"(r[3]) : "r"(addr));
}
__device__ __forceinline__ void mma_f16(float* d, const uint32_t* a,
                                        uint32_t b0, uint32_t b1) {
    asm volatile(
        "mma.sync.aligned.m16n8k16.row.col.f32.f16.f16.f32 "
        "{%0,%1,%2,%3}, {%4,%5,%6,%7}, {%8,%9}, {%0,%1,%2,%3};"
        : "+f"(d[0]), "+f"(d[1]), "+f"(d[2]), "+f"(d[3])
        : "r"(a[0]), "r"(a[1]), "r"(a[2]), "r"(a[3]), "r"(b0), "r"(b1));
}

// ---------------- small utility kernels -----------------------------------
__global__ void zero_int(int* p, int n) {
    int i = blockIdx.x * blockDim.x + threadIdx.x;
    if (i < n) p[i] = 0;
}

__global__ void zero_pad_h(__half* a, __half* b) {
    int i = blockIdx.x * blockDim.x + threadIdx.x;
    int n = (NPAD - NN) * CC;
    if (i < n) {
        int off = NN * CC + i;
        a[off] = __float2half(0.f);
        b[off] = __float2half(0.f);
    }
}

__global__ void count_k(const int* __restrict__ dst, int* __restrict__ cnt) {
    int e = blockIdx.x * blockDim.x + threadIdx.x;
    if (e < EE) {
        int d = dst[e];
        d = min(max(d, 0), NN - 1);
        atomicAdd(&cnt[d], 1);
    }
}

__global__ void scan_block(const int* __restrict__ cnt, int* __restrict__ excl,
                           int* __restrict__ bsum, int n) {
    __shared__ int sm[1024];
    int t = threadIdx.x;
    int g = blockIdx.x * 1024 + t;
    int v = (g < n) ? cnt[g] : 0;
    sm[t] = v;
    __syncthreads();
    for (int off = 1; off < 1024; off <<= 1) {
        int tv = 0;
        if (t >= off) tv = sm[t - off];
        __syncthreads();
        if (t >= off) sm[t] += tv;
        __syncthreads();
    }
    if (g < n) excl[g] = sm[t] - v;
    if (t == 1023) bsum[blockIdx.x] = sm[1023];
}

__global__ void scan_sums(int* bsum, int nb) {
    int run = 0;
    for (int i = 0; i < nb; i++) { int t = bsum[i]; bsum[i] = run; run += t; }
}

__global__ void add_off(int* __restrict__ rowptr, const int* __restrict__ bsum, int n) {
    int g = blockIdx.x * blockDim.x + threadIdx.x;
    if (g < n) rowptr[g] += bsum[g >> 10];
    if (g == 0) rowptr[n] = EE;
}

__global__ void fill_k(const int* __restrict__ src, const int* __restrict__ dst,
                       const int* __restrict__ rowptr, int* __restrict__ cur,
                       int* __restrict__ perm) {
    int e = blockIdx.x * blockDim.x + threadIdx.x;
    if (e < EE) {
        int d = dst[e];
        d = min(max(d, 0), NN - 1);
        int s = src[e];
        s = min(max(s, 0), NN - 1);
        int pos = rowptr[d] + atomicAdd(&cur[d], 1);
        if (pos >= 0 && pos < EE) perm[pos] = s;
    }
}

// ---------------- W_comb = W_ih @ W_lin (fp32, once) -----------------------
__global__ void wcomb_k(const float* __restrict__ W_ih, const float* __restrict__ W_lin,
                        float* __restrict__ W_comb) {
    int i = blockIdx.x;
    int j = threadIdx.x;
    float s = 0.f;
    #pragma unroll 8
    for (int k = 0; k < 128; k++)
        s += W_ih[i * 128 + k] * W_lin[k * 128 + j];
    W_comb[i * 128 + j] = s;
}

// ---------------- fp32 -> fp16 conversion ----------------------------------
__global__ void conv_h(const float* __restrict__ x, __half* __restrict__ o, int n4) {
    int i = blockIdx.x * blockDim.x + threadIdx.x;
    if (i >= n4) return;
    float4 v = ((const float4*)x)[i];
    __half2* o2 = (__half2*)o;
    o2[i * 2 + 0] = __floats2half2_rn(v.x, v.y);
    o2[i * 2 + 1] = __floats2half2_rn(v.z, v.w);
}

// ---------------- single-fp16 GEMM, 128x128 tile, staged epilogue ----------
// Y[NPAD, M] = A[NPAD,128] @ (B[M,128])^T  (fp16 in, fp32 acc, fp16 out)
// 256 threads, 8 warps (4 row-slabs x 2 col-slabs), warp tile 32x64:
// per warp per kstep 6 ldsm4 (3KB) for 16 MMAs -> 21.3 FLOP/B (vs 16 before).
// smem 69632 B -> 2 CTAs/SM; __launch_bounds__(256,2) caps regs at 128.
#define LDSB 136
#define ROWB (LDSB * 2)
#define T128 (128 * LDSB)                      // halves per 128x136 tile
#define G1_SMEM (2 * T128 * 2)                 // 69632 bytes
#define STG 136                                 // staging row stride (halves)

__global__ __launch_bounds__(256, 2)
void gemm_h1(const __half* __restrict__ A0, const __half* __restrict__ B0,
             __half* __restrict__ Y0,
             const __half* __restrict__ A1, const __half* __restrict__ B1,
             __half* __restrict__ Y1, int M) {
    extern __shared__ __half smh[];
    __half* As = smh;
    __half* Bs = smh + T128;

    const __half* A = blockIdx.z ? A1 : A0;
    const __half* B = blockIdx.z ? B1 : B0;
    __half* Y = blockIdx.z ? Y1 : Y0;

    int row0 = blockIdx.x * 128;
    int col0 = blockIdx.y * 128;
    int t = threadIdx.x;

    // A,B tiles: each 128 rows x 16 uint4 = 2048 uint4; 8 per thread per tile
    {
        const uint4* gA = (const uint4*)(A + (size_t)row0 * 128);
        const uint4* gB = (const uint4*)(B + (size_t)col0 * 128);
        #pragma unroll
        for (int i = 0; i < 8; i++) {
            int idx = t + i * 256;
            int r = idx >> 4, c = idx & 15;
            ((uint4*)((char*)As + r * ROWB))[c] = gA[idx];
            ((uint4*)((char*)Bs + r * ROWB))[c] = gB[idx];
        }
    }
    __syncthreads();

    int lane = t & 31;
    int wid = t >> 5;
    int wm = wid & 3;       // 4 x 32-row slabs
    int wn = wid >> 2;      // 2 x 64-col slabs

    uint32_t laneOff = (uint32_t)((lane & 15) * ROWB + (lane >> 4) * 16);
    uint32_t aP = smem_u32(As) + (uint32_t)(wm * 32) * ROWB + laneOff;
    uint32_t bP = smem_u32(Bs) + (uint32_t)(wn * 64) * ROWB + laneOff;

    float acc[2][8][4];
    #pragma unroll
    for (int i = 0; i < 2; i++)
        #pragma unroll
        for (int j = 0; j < 8; j++)
            #pragma unroll
            for (int q = 0; q < 4; q++) acc[i][j][q] = 0.f;

    #pragma unroll
    for (int ks = 0; ks < 8; ks++) {
        uint32_t kb = ks * 32;
        uint32_t a0[4], a1[4], p[4][4];
        ldsm4(a0, aP + kb);
        ldsm4(a1, aP + 16 * ROWB + kb);
        #pragma unroll
        for (int q = 0; q < 4; q++)
            ldsm4(p[q], bP + (uint32_t)(q * 16) * ROWB + kb);
        #pragma unroll
        for (int q = 0; q < 4; q++) {
            mma_f16(acc[0][2 * q + 0], a0, p[q][0], p[q][2]);
            mma_f16(acc[0][2 * q + 1], a0, p[q][1], p[q][3]);
            mma_f16(acc[1][2 * q + 0], a1, p[q][0], p[q][2]);
            mma_f16(acc[1][2 * q + 1], a1, p[q][1], p[q][3]);
        }
    }

    // ---- staged epilogue: acc -> smem (conflict-free) -> coalesced global --
    __syncthreads();
    __half* stg = smh;                     // 128 x STG halves = 34816 B
    {
        int rbase = wm * 32 + (lane >> 2);
        int cbase = wn * 64 + (lane & 3) * 2;
        #pragma unroll
        for (int i = 0; i < 2; i++) {
            #pragma unroll
            for (int j = 0; j < 8; j++) {
                *(__half2*)&stg[(rbase + i * 16) * STG + cbase + j * 8] =
                    __floats2half2_rn(acc[i][j][0], acc[i][j][1]);
                *(__half2*)&stg[(rbase + i * 16 + 8) * STG + cbase + j * 8] =
                    __floats2half2_rn(acc[i][j][2], acc[i][j][3]);
            }
        }
    }
    __syncthreads();
    {
        #pragma unroll
        for (int it = 0; it < 8; it++) {
            int idx = t + it * 256;        // 0..2047
            int r = idx >> 4;
            int c16 = idx & 15;
            uint4 v = *(const uint4*)&stg[r * STG + c16 * 8];
            *(uint4*)&Y[(size_t)(row0 + r) * M + col0 + c16 * 8] = v;
        }
    }
}

// ---------------- aggregation: gather fp16 state, fp32 accum, fp16 out -----
__global__ __launch_bounds__(128)
void aggregate_h(const __half* __restrict__ st, const int* __restrict__ rowptr,
                 const int* __restrict__ perm, __half* __restrict__ ph) {
    int i = blockIdx.x * 2 + (threadIdx.x >> 6);
    int c2 = threadIdx.x & 63;
    if (i >= NN) return;
    const __half2* st2 = (const __half2*)st;
    int s0 = rowptr[i], s1 = rowptr[i + 1];
    float ax0 = 0.f, ay0 = 0.f, ax1 = 0.f, ay1 = 0.f;
    int e = s0;
    for (; e + 1 < s1; e += 2) {
        int p0 = perm[e], p1 = perm[e + 1];
        float2 f0 = __half22float2(st2[p0 * 64 + c2]);
        float2 f1 = __half22float2(st2[p1 * 64 + c2]);
        ax0 += f0.x; ay0 += f0.y;
        ax1 += f1.x; ay1 += f1.y;
    }
    if (e < s1) {
        float2 f0 = __half22float2(st2[perm[e] * 64 + c2]);
        ax0 += f0.x; ay0 += f0.y;
    }
    ((__half2*)ph)[i * 64 + c2] = __floats2half2_rn(ax0 + ax1, ay0 + ay1);
}

// ---------------- GRU elementwise (fp16 gates in; fp32 state + fp16 copy) --
__global__ void gru_k(const __half* __restrict__ gi, const __half* __restrict__ gh,
                      const float* __restrict__ b_ih, const float* __restrict__ b_hh,
                      const float* __restrict__ h, float* __restrict__ out,
                      __half* __restrict__ oh, int n4) {
    int idx = blockIdx.x * blockDim.x + threadIdx.x;
    if (idx >= n4) return;
    int i = idx >> 5;
    int c4 = (idx & 31) * 4;
    const __half2* gir = (const __half2*)(gi + (size_t)i * 384 + c4);
    const __half2* ghr = (const __half2*)(gh + (size_t)i * 384 + c4);
    float2 ir0 = __half22float2(gir[0]),  ir1 = __half22float2(gir[1]);
    float2 iz0 = __half22float2(gir[64]), iz1 = __half22float2(gir[65]);
    float2 in0 = __half22float2(gir[128]), in1 = __half22float2(gir[129]);
    float2 hr0 = __half22float2(ghr[0]),  hr1 = __half22float2(ghr[1]);
    float2 hz0 = __half22float2(ghr[64]), hz1 = __half22float2(ghr[65]);
    float2 hn0 = __half22float2(ghr[128]), hn1 = __half22float2(ghr[129]);
    float ir[4] = {ir0.x, ir0.y, ir1.x, ir1.y};
    float iz[4] = {iz0.x, iz0.y, iz1.x, iz1.y};
    float in_[4] = {in0.x, in0.y, in1.x, in1.y};
    float hr[4] = {hr0.x, hr0.y, hr1.x, hr1.y};
    float hz[4] = {hz0.x, hz0.y, hz1.x, hz1.y};
    float hn[4] = {hn0.x, hn0.y, hn1.x, hn1.y};

    float4 bir = *(const float4*)(b_ih + c4);
    float4 biz = *(const float4*)(b_ih + 128 + c4);
    float4 bin = *(const float4*)(b_ih + 256 + c4);
    float4 bhr = *(const float4*)(b_hh + c4);
    float4 bhz = *(const float4*)(b_hh + 128 + c4);
    float4 bhn = *(const float4*)(b_hh + 256 + c4);
    float4 hv = *(const float4*)(h + (size_t)i * 128 + c4);

    float o[4];
    #pragma unroll
    for (int q = 0; q < 4; q++) {
        float irq = (ir[q] + (&bir.x)[q]) + (hr[q] + (&bhr.x)[q]);
        float izq = (iz[q] + (&biz.x)[q]) + (hz[q] + (&bhz.x)[q]);
        float inq = in_[q] + (&bin.x)[q];
        float hnq = hn[q] + (&bhn.x)[q];
        float r = 1.f / (1.f + expf(-irq));
        float z = 1.f / (1.f + expf(-izq));
        float nval = tanhf(inq + r * hnq);
        o[q] = (1.f - z) * nval + z * (&hv.x)[q];
    }
    *(float4*)(out + (size_t)i * 128 + c4) = make_float4(o[0], o[1], o[2], o[3]);
    __half2* ohp = (__half2*)(oh + (size_t)i * 128 + c4);
    ohp[0] = __floats2half2_rn(o[0], o[1]);
    ohp[1] = __floats2half2_rn(o[2], o[3]);
}

// ---------------- launcher --------------------------------------------------
extern "C" void kernel_launch(void* const* d_in, const int* in_sizes, int n_in,
                              void* d_out, int out_size) {
    const float* x     = (const float*)d_in[0];
    const int*   ei    = (const int*)d_in[1];
    const float* W_lin = (const float*)d_in[2];
    const float* W_ih  = (const float*)d_in[3];
    const float* W_hh  = (const float*)d_in[4];
    const float* b_ih  = (const float*)d_in[5];
    const float* b_hh  = (const float*)d_in[6];
    float* out = (float*)d_out;

    const int* src = ei;
    const int* dst = ei + EE;

    float *sA_, *sB_, *wc_;
    int *cnt_, *rp_, *perm_, *bsum_;
    __half *gi_, *gh_, *sxh_, *sph_, *whhh_, *wch_;
    cudaGetSymbolAddress((void**)&sA_,   g_sA);
    cudaGetSymbolAddress((void**)&sB_,   g_sB);
    cudaGetSymbolAddress((void**)&gi_,   g_gi);
    cudaGetSymbolAddress((void**)&gh_,   g_gh);
    cudaGetSymbolAddress((void**)&wc_,   g_wcomb);
    cudaGetSymbolAddress((void**)&cnt_,  g_cnt);
    cudaGetSymbolAddress((void**)&rp_,   g_rowptr);
    cudaGetSymbolAddress((void**)&perm_, g_perm);
    cudaGetSymbolAddress((void**)&bsum_, g_bsum);
    cudaGetSymbolAddress((void**)&sxh_,  g_sxh);
    cudaGetSymbolAddress((void**)&sph_,  g_sph);
    cudaGetSymbolAddress((void**)&whhh_, g_whh_h);
    cudaGetSymbolAddress((void**)&wch_,  g_wc_h);

    cudaFuncSetAttribute(gemm_h1, cudaFuncAttributeMaxDynamicSharedMemorySize, G1_SMEM);

    cudaStream_t s2;
    cudaStreamCreateWithFlags(&s2, cudaStreamNonBlocking);
    cudaEvent_t evRoot, evCSR, evGru1, evGh1, evGru2, evGh2;
    cudaEventCreateWithFlags(&evRoot, cudaEventDisableTiming);
    cudaEventCreateWithFlags(&evCSR,  cudaEventDisableTiming);
    cudaEventCreateWithFlags(&evGru1, cudaEventDisableTiming);
    cudaEventCreateWithFlags(&evGh1,  cudaEventDisableTiming);
    cudaEventCreateWithFlags(&evGru2, cudaEventDisableTiming);
    cudaEventCreateWithFlags(&evGh2,  cudaEventDisableTiming);

    const int NB_SCAN = (NN + 1023) / 1024;
    const int N4 = NN * CC / 4;
    const int NAGG = (NN + 1) / 2;
    const dim3 gg1(RTILES, 3, 1);             // 128x128 tiles over [NPAD, 384]

    // ---- prologue; gemm_h1 = my launch #4 (ncu -s 5 -c 1 lands there) ----
    conv_h<<<(N4 + 255) / 256, 256>>>(x, sxh_, N4);                                   // 1
    conv_h<<<(384 * CC / 4 + 255) / 256, 256>>>(W_hh, whhh_, 384 * CC / 4);           // 2
    zero_pad_h<<<((NPAD - NN) * CC + 255) / 256, 256>>>(sxh_, sph_);                  // 3
    gemm_h1<<<gg1, 256, G1_SMEM>>>(sxh_, whhh_, gh_,                                  // 4 (profiled)
                                   sxh_, whhh_, gh_, 384);
    wcomb_k<<<384, 128>>>(W_ih, W_lin, wc_);
    conv_h<<<(384 * CC / 4 + 255) / 256, 256>>>(wc_, wch_, 384 * CC / 4);

    // ---- CSR build on side stream (overlaps prologue) ----
    cudaEventRecord(evRoot, 0);
    cudaStreamWaitEvent(s2, evRoot, 0);
    zero_int <<<(NN + 255) / 256, 256, 0, s2>>>(cnt_, NN);
    count_k  <<<(EE + 255) / 256, 256, 0, s2>>>(dst, cnt_);
    scan_block<<<NB_SCAN, 1024, 0, s2>>>(cnt_, rp_, bsum_, NN);
    scan_sums <<<1, 1, 0, s2>>>(bsum_, NB_SCAN);
    add_off   <<<(NN + 255) / 256, 256, 0, s2>>>(rp_, bsum_, NN);
    zero_int  <<<(NN + 255) / 256, 256, 0, s2>>>(cnt_, NN);
    fill_k    <<<(EE + 255) / 256, 256, 0, s2>>>(src, dst, rp_, cnt_, perm_);
    cudaEventRecord(evCSR, s2);
    cudaStreamWaitEvent(0, evCSR, 0);

    // ---- step 0 (gh computed at launch 4) ----
    aggregate_h<<<NAGG, 128>>>(sxh_, rp_, perm_, sph_);
    gemm_h1<<<gg1, 256, G1_SMEM>>>(sph_, wch_, gi_,
                                   sph_, wch_, gi_, 384);
    gru_k<<<(N4 + 255) / 256, 256>>>(gi_, gh_, b_ih, b_hh, x, sA_, sxh_, N4);

    // ---- step 1: gh GEMM (s2) overlaps aggregate (main) ----
    cudaEventRecord(evGru1, 0);
    cudaStreamWaitEvent(s2, evGru1, 0);
    gemm_h1<<<gg1, 256, G1_SMEM, s2>>>(sxh_, whhh_, gh_,
                                       sxh_, whhh_, gh_, 384);
    cudaEventRecord(evGh1, s2);
    aggregate_h<<<NAGG, 128>>>(sxh_, rp_, perm_, sph_);
    gemm_h1<<<gg1, 256, G1_SMEM>>>(sph_, wch_, gi_,
                                   sph_, wch_, gi_, 384);
    cudaStreamWaitEvent(0, evGh1, 0);
    gru_k<<<(N4 + 255) / 256, 256>>>(gi_, gh_, b_ih, b_hh, sA_, sB_, sxh_, N4);

    // ---- step 2 ----
    cudaEventRecord(evGru2, 0);
    cudaStreamWaitEvent(s2, evGru2, 0);
    gemm_h1<<<gg1, 256, G1_SMEM, s2>>>(sxh_, whhh_, gh_,
                                       sxh_, whhh_, gh_, 384);
    cudaEventRecord(evGh2, s2);
    aggregate_h<<<NAGG, 128>>>(sxh_, rp_, perm_, sph_);
    gemm_h1<<<gg1, 256, G1_SMEM>>>(sph_, wch_, gi_,
                                   sph_, wch_, gi_, 384);
    cudaStreamWaitEvent(0, evGh2, 0);
    gru_k<<<(N4 + 255) / 256, 256>>>(gi_, gh_, b_ih, b_hh, sB_, out, sxh_, N4);
}